// round 1
// baseline (speedup 1.0000x reference)
#include <cuda_runtime.h>
#include <math.h>

// ---------------- problem constants ----------------
#define TT    2048
#define H     16
#define NOPE  128
#define ROPE  64
#define VDIM  128
#define RANK  512
#define QIN   1536
#define HID   7168
#define DQK   576            // RANK + ROPE
#define QFW   (H * (NOPE + ROPE))   // 3072

__device__ __constant__ float d_dummy; // keep compiler honest

static __device__ float g_qf  [(size_t)TT * QFW];              // 2048*3072
static __device__ float g_qcat[(size_t)TT * H * DQK];          // 2048*16*576
static __device__ float g_kcat[(size_t)TT * DQK];              // 2048*576
static __device__ float g_S   [(size_t)H * TT * TT];           // 16*2048*2048 (scores -> probs)
static __device__ float g_olat[(size_t)TT * H * RANK];         // 2048*16*512
static __device__ float g_o   [(size_t)TT * H * VDIM];         // 2048*2048

// ---------------- generic strided fp32 GEMM ----------------
// C[m,n] = alpha * sum_k A[m*sa_m + k] * B[k*sb_k + n*sb_n]
// (A is always k-contiguous; B is k-contiguous iff sb_k==1, else n-contiguous with sb_n==1)
// M,N given by grid (M = gridDim.y*128, N = gridDim.x*128), K multiple of 16.
__global__ __launch_bounds__(256, 2)
void gemm_generic(const float* __restrict__ A, const float* __restrict__ B,
                  float* __restrict__ C, int K,
                  int sa_m, int sb_k, int sb_n, int sc_m,
                  long long aBS, long long bBS, long long cBS, float alpha)
{
    __shared__ float As[16][132];
    __shared__ float Bs[16][132];

    const int tid = threadIdx.x;
    const int tx  = tid & 15;      // n-direction (8 cols each)
    const int ty  = tid >> 4;      // m-direction (8 rows each)
    const int m0  = blockIdx.y * 128;
    const int n0  = blockIdx.x * 128;

    A += (long long)blockIdx.z * aBS + (long long)m0 * sa_m;
    B += (long long)blockIdx.z * bBS;
    C += (long long)blockIdx.z * cBS + (long long)m0 * sc_m + n0;

    float acc[8][8];
#pragma unroll
    for (int i = 0; i < 8; i++)
#pragma unroll
        for (int j = 0; j < 8; j++) acc[i][j] = 0.0f;

    const int la_k = tid & 15;     // A load: k inner (coalesced, sa_k==1)
    const int la_m = tid >> 4;

    const bool bKContig = (sb_k == 1);

    for (int kt = 0; kt < K; kt += 16) {
        // load A tile 128x16 -> As[k][m]
#pragma unroll
        for (int i = 0; i < 8; i++) {
            int m = la_m + i * 16;
            As[la_k][m] = A[(long long)m * sa_m + (kt + la_k)];
        }
        // load B tile 16x128 -> Bs[k][n]
        if (bKContig) {
#pragma unroll
            for (int i = 0; i < 8; i++) {
                int n = la_m + i * 16;
                Bs[la_k][n] = B[(long long)(n0 + n) * sb_n + (kt + la_k)];
            }
        } else {
            int nb = tid & 127;
            int kb = tid >> 7;
#pragma unroll
            for (int i = 0; i < 8; i++) {
                int k = kb + i * 2;
                Bs[k][nb] = B[(long long)(kt + k) * sb_k + (n0 + nb)];
            }
        }
        __syncthreads();

#pragma unroll
        for (int k = 0; k < 16; k++) {
            float4 a0 = *(const float4*)&As[k][ty * 8];
            float4 a1 = *(const float4*)&As[k][ty * 8 + 4];
            float4 b0 = *(const float4*)&Bs[k][tx * 8];
            float4 b1 = *(const float4*)&Bs[k][tx * 8 + 4];
            float av[8] = {a0.x, a0.y, a0.z, a0.w, a1.x, a1.y, a1.z, a1.w};
            float bv[8] = {b0.x, b0.y, b0.z, b0.w, b1.x, b1.y, b1.z, b1.w};
#pragma unroll
            for (int i = 0; i < 8; i++)
#pragma unroll
                for (int j = 0; j < 8; j++)
                    acc[i][j] = fmaf(av[i], bv[j], acc[i][j]);
        }
        __syncthreads();
    }

#pragma unroll
    for (int i = 0; i < 8; i++) {
        float* crow = C + (long long)(ty * 8 + i) * sc_m + tx * 8;
        float4 v0 = make_float4(alpha * acc[i][0], alpha * acc[i][1],
                                alpha * acc[i][2], alpha * acc[i][3]);
        float4 v1 = make_float4(alpha * acc[i][4], alpha * acc[i][5],
                                alpha * acc[i][6], alpha * acc[i][7]);
        *(float4*)(crow)     = v0;
        *(float4*)(crow + 4) = v1;
    }
}

// ---------------- RoPE + concat packing ----------------
// Builds kcat[t, 0:512]=k_c, kcat[t,512:576]=rope(k_pe)
// and    qcat[t,h,512:576]=SCALE*rope(q_pe)   (q_lat part written by GEMM)
__global__ void rope_pack(const float* __restrict__ qf, const float* __restrict__ k_c,
                          const float* __restrict__ k_pe, const int* __restrict__ pos,
                          const float* __restrict__ cosc, const float* __restrict__ sinc,
                          float* __restrict__ qcat, float* __restrict__ kcat, float scale)
{
    int t = blockIdx.x;
    int p = pos[t];
    const float* cs = cosc + (long long)p * (ROPE / 2);
    const float* sn = sinc + (long long)p * (ROPE / 2);

    for (int i = threadIdx.x; i < RANK; i += blockDim.x)
        kcat[(long long)t * DQK + i] = k_c[(long long)t * RANK + i];

    for (int j = threadIdx.x; j < ROPE / 2; j += blockDim.x) {
        float x1 = k_pe[(long long)t * ROPE + j];
        float x2 = k_pe[(long long)t * ROPE + j + ROPE / 2];
        float c = cs[j], s = sn[j];
        kcat[(long long)t * DQK + RANK + j]            = x1 * c - x2 * s;
        kcat[(long long)t * DQK + RANK + ROPE / 2 + j] = x2 * c + x1 * s;
    }

    for (int idx = threadIdx.x; idx < H * (ROPE / 2); idx += blockDim.x) {
        int h = idx / (ROPE / 2);
        int j = idx % (ROPE / 2);
        float x1 = qf[(long long)t * QFW + h * (NOPE + ROPE) + NOPE + j];
        float x2 = qf[(long long)t * QFW + h * (NOPE + ROPE) + NOPE + ROPE / 2 + j];
        float c = cs[j], s = sn[j];
        long long base = ((long long)t * H + h) * DQK + RANK;
        qcat[base + j]            = scale * (x1 * c - x2 * s);
        qcat[base + ROPE / 2 + j] = scale * (x2 * c + x1 * s);
    }
}

// ---------------- causal softmax (in-place on S) ----------------
__global__ __launch_bounds__(256)
void softmax_causal(float* __restrict__ S, const int* __restrict__ pos)
{
    const int t = blockIdx.x;
    const int h = blockIdx.y;
    float* row = S + ((long long)h * TT + t) * TT;
    const int pq = pos[t];

    __shared__ float red[256];
    const int tid = threadIdx.x;

    float v[8];
    float m = -1e30f;
#pragma unroll
    for (int i = 0; i < 8; i++) {
        int s = tid + i * 256;
        v[i] = (pos[s] <= pq) ? row[s] : -1e30f;
        m = fmaxf(m, v[i]);
    }
    red[tid] = m; __syncthreads();
    for (int w = 128; w > 0; w >>= 1) {
        if (tid < w) red[tid] = fmaxf(red[tid], red[tid + w]);
        __syncthreads();
    }
    m = red[0];
    __syncthreads();

    float sum = 0.0f;
#pragma unroll
    for (int i = 0; i < 8; i++) {
        v[i] = __expf(v[i] - m);     // masked entries: exp(-huge) == 0
        sum += v[i];
    }
    red[tid] = sum; __syncthreads();
    for (int w = 128; w > 0; w >>= 1) {
        if (tid < w) red[tid] += red[tid + w];
        __syncthreads();
    }
    float inv = 1.0f / red[0];

#pragma unroll
    for (int i = 0; i < 8; i++)
        row[tid + i * 256] = v[i] * inv;
}

// ---------------- launch ----------------
extern "C" void kernel_launch(void* const* d_in, const int* in_sizes, int n_in,
                              void* d_out, int out_size)
{
    const float* q     = (const float*)d_in[0];
    const float* k_c   = (const float*)d_in[1];
    const float* k_pe  = (const float*)d_in[2];
    const int*   pos   = (const int*)  d_in[3];
    const float* wq    = (const float*)d_in[4];
    const float* kv_b  = (const float*)d_in[5];
    const float* wo    = (const float*)d_in[6];
    const float* cosc  = (const float*)d_in[7];
    const float* sinc  = (const float*)d_in[8];
    float* out = (float*)d_out;

    float *qf, *qcat, *kcat, *S, *olat, *o;
    cudaGetSymbolAddress((void**)&qf,   g_qf);
    cudaGetSymbolAddress((void**)&qcat, g_qcat);
    cudaGetSymbolAddress((void**)&kcat, g_kcat);
    cudaGetSymbolAddress((void**)&S,    g_S);
    cudaGetSymbolAddress((void**)&olat, g_olat);
    cudaGetSymbolAddress((void**)&o,    g_o);

    const float scale = rsqrtf((float)(NOPE + ROPE));

    // 1) qf = q @ wq^T : M=2048 N=3072 K=1536
    gemm_generic<<<dim3(QFW / 128, TT / 128, 1), 256>>>(
        q, wq, qf, QIN,
        /*sa_m*/ QIN, /*sb_k*/ 1, /*sb_n*/ QIN, /*sc_m*/ QFW,
        0, 0, 0, 1.0f);

    // 2) rope + pack
    rope_pack<<<TT, 256>>>(qf, k_c, k_pe, pos, cosc, sinc, qcat, kcat, scale);

    // 3) q_lat (per head): M=2048 N=512 K=128, alpha=SCALE -> qcat[:, h, 0:512]
    gemm_generic<<<dim3(RANK / 128, TT / 128, H), 256>>>(
        qf, kv_b, qcat, NOPE,
        /*sa_m*/ QFW, /*sb_k*/ RANK, /*sb_n*/ 1, /*sc_m*/ H * DQK,
        /*aBS*/ (long long)(NOPE + ROPE), /*bBS*/ (long long)(NOPE + VDIM) * RANK,
        /*cBS*/ (long long)DQK, scale);

    // 4) S_h = Qcat_h @ Kcat^T : M=2048 N=2048 K=576
    gemm_generic<<<dim3(TT / 128, TT / 128, H), 256>>>(
        qcat, kcat, S, DQK,
        /*sa_m*/ H * DQK, /*sb_k*/ 1, /*sb_n*/ DQK, /*sc_m*/ TT,
        /*aBS*/ (long long)DQK, /*bBS*/ 0, /*cBS*/ (long long)TT * TT, 1.0f);

    // 5) causal softmax in-place
    softmax_causal<<<dim3(TT, H), 256>>>(S, pos);

    // 6) olat_h = P_h @ k_c : M=2048 N=512 K=2048
    gemm_generic<<<dim3(RANK / 128, TT / 128, H), 256>>>(
        S, k_c, olat, TT,
        /*sa_m*/ TT, /*sb_k*/ RANK, /*sb_n*/ 1, /*sc_m*/ H * RANK,
        /*aBS*/ (long long)TT * TT, /*bBS*/ 0, /*cBS*/ (long long)RANK, 1.0f);

    // 7) o[:, h*128:(h+1)*128] = olat_h @ w_uv_h : M=2048 N=128 K=512
    gemm_generic<<<dim3(VDIM / 128, TT / 128, H), 256>>>(
        olat, kv_b + (long long)NOPE * RANK, o, RANK,
        /*sa_m*/ H * RANK, /*sb_k*/ 1, /*sb_n*/ RANK, /*sc_m*/ H * VDIM,
        /*aBS*/ (long long)RANK, /*bBS*/ (long long)(NOPE + VDIM) * RANK,
        /*cBS*/ (long long)VDIM, 1.0f);

    // 8) out = o @ wo^T : M=2048 N=7168 K=2048
    gemm_generic<<<dim3(HID / 128, TT / 128, 1), 256>>>(
        o, wo, out, H * VDIM,
        /*sa_m*/ H * VDIM, /*sb_k*/ 1, /*sb_n*/ H * VDIM, /*sc_m*/ HID,
        0, 0, 0, 1.0f);
}

// round 3
// speedup vs baseline: 2.1652x; 2.1652x over previous
#include <cuda_runtime.h>
#include <cuda_bf16.h>
#include <stdint.h>
#include <math.h>

// ---------------- problem constants ----------------
#define TT    2048
#define H     16
#define NOPE  128
#define ROPE  64
#define VDIM  128
#define RANK  512
#define QIN   1536
#define HID   7168
#define DQK   576            // RANK + ROPE
#define QFW   (H * (NOPE + ROPE))   // 3072

static __device__ float g_qf  [(size_t)TT * QFW];
static __device__ float g_qcat[(size_t)TT * H * DQK];
static __device__ float g_kcat[(size_t)TT * DQK];
static __device__ float g_S   [(size_t)H * TT * TT];
static __device__ float g_olat[(size_t)TT * H * RANK];
static __device__ float g_o   [(size_t)TT * H * VDIM];

// ---------------- helpers ----------------
__device__ __forceinline__ uint32_t pack_hi(float a, float b, float& ra, float& rb) {
    __nv_bfloat16 ha = __float2bfloat16(a);
    __nv_bfloat16 hb = __float2bfloat16(b);
    ra = a - __bfloat162float(ha);
    rb = b - __bfloat162float(hb);
    __nv_bfloat162 p;
    p.x = ha; p.y = hb;
    return *(uint32_t*)&p;
}
__device__ __forceinline__ uint32_t pack_lo(float a, float b) {
    __nv_bfloat162 p;
    p.x = __float2bfloat16(a); p.y = __float2bfloat16(b);
    return *(uint32_t*)&p;
}

#define MMA_BF16(C, A, B0, B1)                                              \
    asm volatile(                                                           \
        "mma.sync.aligned.m16n8k16.row.col.f32.bf16.bf16.f32 "              \
        "{%0,%1,%2,%3},{%4,%5,%6,%7},{%8,%9},{%0,%1,%2,%3};\n"              \
        : "+f"(C[0]), "+f"(C[1]), "+f"(C[2]), "+f"(C[3])                    \
        : "r"(A[0]), "r"(A[1]), "r"(A[2]), "r"(A[3]), "r"(B0), "r"(B1));

// ---------------- compensated-bf16 tensor-core GEMM ----------------
// C[m,n] = alpha * sum_k A[m*sa_m + k] * B[...]
// A: k-contiguous, row stride sa_m. B: k-contig [n][k] if sb_k==1 (stride sb_n),
// else n-contig [k][n] (stride sb_k).
// mode bit0: causal tile skip (skip if n0 > m0). mode bit1: limit K to m0+128.
__global__ __launch_bounds__(256, 1)
void gemm_bf16x3(const float* __restrict__ A, const float* __restrict__ B,
                 float* __restrict__ C, int K,
                 int sa_m, int sb_k, int sb_n, int sc_m,
                 long long aBS, long long bBS, long long cBS,
                 float alpha, int mode)
{
    const int m0 = blockIdx.y * 128;
    const int n0 = blockIdx.x * 128;
    if ((mode & 1) && n0 > m0) return;
    int Keff = K;
    if (mode & 2) { int kl = m0 + 128; if (kl < Keff) Keff = kl; }

    A += (long long)blockIdx.z * aBS + (long long)m0 * sa_m;
    B += (long long)blockIdx.z * bBS;
    C += (long long)blockIdx.z * cBS + (long long)m0 * sc_m + n0;

    __shared__ uint32_t sAhi[128][17];
    __shared__ uint32_t sAlo[128][17];
    __shared__ uint32_t sBhi[128][17];
    __shared__ uint32_t sBlo[128][17];

    const int tid  = threadIdx.x;
    const int lane = tid & 31;
    const int wid  = tid >> 5;
    const int warpM = (wid & 3) * 32;
    const int warpN = (wid >> 2) * 64;
    const int g   = lane >> 2;
    const int tig = lane & 3;

    float acc[2][8][4];
#pragma unroll
    for (int mi = 0; mi < 2; mi++)
#pragma unroll
        for (int ni = 0; ni < 8; ni++)
#pragma unroll
            for (int j = 0; j < 4; j++) acc[mi][ni][j] = 0.0f;

    const int arow = tid >> 1;
    const int akh  = (tid & 1) * 16;
    const bool bK  = (sb_k == 1);

    for (int kt = 0; kt < Keff; kt += 32) {
        // ---- stage A (fp32 -> bf16 hi/lo) ----
#pragma unroll
        for (int i = 0; i < 4; i++) {
            float4 v = *(const float4*)&A[(long long)arow * sa_m + kt + akh + i * 4];
            int c0 = (akh >> 1) + i * 2;
            float rx, ry, rz, rw;
            sAhi[arow][c0]     = pack_hi(v.x, v.y, rx, ry);
            sAhi[arow][c0 + 1] = pack_hi(v.z, v.w, rz, rw);
            sAlo[arow][c0]     = pack_lo(rx, ry);
            sAlo[arow][c0 + 1] = pack_lo(rz, rw);
        }
        // ---- stage B ----
        if (bK) {
#pragma unroll
            for (int i = 0; i < 4; i++) {
                float4 v = *(const float4*)&B[(long long)(n0 + arow) * sb_n + kt + akh + i * 4];
                int c0 = (akh >> 1) + i * 2;
                float rx, ry, rz, rw;
                sBhi[arow][c0]     = pack_hi(v.x, v.y, rx, ry);
                sBhi[arow][c0 + 1] = pack_hi(v.z, v.w, rz, rw);
                sBlo[arow][c0]     = pack_lo(rx, ry);
                sBlo[arow][c0 + 1] = pack_lo(rz, rw);
            }
        } else {
            __nv_bfloat16* bh = (__nv_bfloat16*)&sBhi[0][0];
            __nv_bfloat16* bl = (__nv_bfloat16*)&sBlo[0][0];
            const int kk = tid >> 5;
            const int n4 = tid & 31;
#pragma unroll
            for (int i = 0; i < 4; i++) {
                int k = kk + i * 8;
                float4 v = *(const float4*)&B[(long long)(kt + k) * sb_k + n0 + n4 * 4];
                float e[4] = {v.x, v.y, v.z, v.w};
#pragma unroll
                for (int jj = 0; jj < 4; jj++) {
                    int n = n4 * 4 + jj;
                    __nv_bfloat16 hv = __float2bfloat16(e[jj]);
                    bh[n * 34 + k] = hv;
                    bl[n * 34 + k] = __float2bfloat16(e[jj] - __bfloat162float(hv));
                }
            }
        }
        __syncthreads();

        // ---- compute ----
#pragma unroll
        for (int ks = 0; ks < 2; ks++) {
            const int cb = tig + ks * 8;
            uint32_t ah[2][4], al[2][4];
#pragma unroll
            for (int mi = 0; mi < 2; mi++) {
                int r = warpM + mi * 16 + g;
                ah[mi][0] = sAhi[r][cb];     ah[mi][1] = sAhi[r + 8][cb];
                ah[mi][2] = sAhi[r][cb + 4]; ah[mi][3] = sAhi[r + 8][cb + 4];
                al[mi][0] = sAlo[r][cb];     al[mi][1] = sAlo[r + 8][cb];
                al[mi][2] = sAlo[r][cb + 4]; al[mi][3] = sAlo[r + 8][cb + 4];
            }
            uint32_t bh[8][2], bl[8][2];
#pragma unroll
            for (int ni = 0; ni < 8; ni++) {
                int r = warpN + ni * 8 + g;
                bh[ni][0] = sBhi[r][cb]; bh[ni][1] = sBhi[r][cb + 4];
                bl[ni][0] = sBlo[r][cb]; bl[ni][1] = sBlo[r][cb + 4];
            }
#pragma unroll
            for (int mi = 0; mi < 2; mi++)
#pragma unroll
                for (int ni = 0; ni < 8; ni++) {
                    MMA_BF16(acc[mi][ni], ah[mi], bh[ni][0], bh[ni][1]);
                    MMA_BF16(acc[mi][ni], ah[mi], bl[ni][0], bl[ni][1]);
                    MMA_BF16(acc[mi][ni], al[mi], bh[ni][0], bh[ni][1]);
                }
        }
        __syncthreads();
    }

    // ---- epilogue ----
#pragma unroll
    for (int mi = 0; mi < 2; mi++)
#pragma unroll
        for (int ni = 0; ni < 8; ni++) {
            int r = warpM + mi * 16 + g;
            int cc = warpN + ni * 8 + 2 * tig;
            float2 v0 = make_float2(alpha * acc[mi][ni][0], alpha * acc[mi][ni][1]);
            float2 v1 = make_float2(alpha * acc[mi][ni][2], alpha * acc[mi][ni][3]);
            *(float2*)&C[(long long)r * sc_m + cc]       = v0;
            *(float2*)&C[(long long)(r + 8) * sc_m + cc] = v1;
        }
}

// ---------------- RoPE + concat packing ----------------
__global__ void rope_pack(const float* __restrict__ qf, const float* __restrict__ k_c,
                          const float* __restrict__ k_pe, const int* __restrict__ pos,
                          const float* __restrict__ cosc, const float* __restrict__ sinc,
                          float* __restrict__ qcat, float* __restrict__ kcat, float scale)
{
    int t = blockIdx.x;
    int p = pos[t];
    const float* cs = cosc + (long long)p * (ROPE / 2);
    const float* sn = sinc + (long long)p * (ROPE / 2);

    for (int i = threadIdx.x; i < RANK; i += blockDim.x)
        kcat[(long long)t * DQK + i] = k_c[(long long)t * RANK + i];

    for (int j = threadIdx.x; j < ROPE / 2; j += blockDim.x) {
        float x1 = k_pe[(long long)t * ROPE + j];
        float x2 = k_pe[(long long)t * ROPE + j + ROPE / 2];
        float c = cs[j], s = sn[j];
        kcat[(long long)t * DQK + RANK + j]            = x1 * c - x2 * s;
        kcat[(long long)t * DQK + RANK + ROPE / 2 + j] = x2 * c + x1 * s;
    }

    for (int idx = threadIdx.x; idx < H * (ROPE / 2); idx += blockDim.x) {
        int h = idx / (ROPE / 2);
        int j = idx % (ROPE / 2);
        float x1 = qf[(long long)t * QFW + h * (NOPE + ROPE) + NOPE + j];
        float x2 = qf[(long long)t * QFW + h * (NOPE + ROPE) + NOPE + ROPE / 2 + j];
        float c = cs[j], s = sn[j];
        long long base = ((long long)t * H + h) * DQK + RANK;
        qcat[base + j]            = scale * (x1 * c - x2 * s);
        qcat[base + ROPE / 2 + j] = scale * (x2 * c + x1 * s);
    }
}

// ---------------- causal softmax (in-place on S) ----------------
__global__ __launch_bounds__(256)
void softmax_causal(float* __restrict__ S, const int* __restrict__ pos)
{
    const int t = blockIdx.x;
    const int h = blockIdx.y;
    float* row = S + ((long long)h * TT + t) * TT;
    const int pq = pos[t];

    __shared__ float red[256];
    const int tid = threadIdx.x;

    float v[8];
    float m = -1e30f;
#pragma unroll
    for (int i = 0; i < 8; i++) {
        int s = tid + i * 256;
        v[i] = (pos[s] <= pq) ? row[s] : -1e30f;
        m = fmaxf(m, v[i]);
    }
    red[tid] = m; __syncthreads();
    for (int w = 128; w > 0; w >>= 1) {
        if (tid < w) red[tid] = fmaxf(red[tid], red[tid + w]);
        __syncthreads();
    }
    m = red[0];
    __syncthreads();

    float sum = 0.0f;
#pragma unroll
    for (int i = 0; i < 8; i++) {
        v[i] = __expf(v[i] - m);
        sum += v[i];
    }
    red[tid] = sum; __syncthreads();
    for (int w = 128; w > 0; w >>= 1) {
        if (tid < w) red[tid] += red[tid + w];
        __syncthreads();
    }
    float inv = 1.0f / red[0];

#pragma unroll
    for (int i = 0; i < 8; i++)
        row[tid + i * 256] = v[i] * inv;
}

// ---------------- launch ----------------
extern "C" void kernel_launch(void* const* d_in, const int* in_sizes, int n_in,
                              void* d_out, int out_size)
{
    const float* q     = (const float*)d_in[0];
    const float* k_c   = (const float*)d_in[1];
    const float* k_pe  = (const float*)d_in[2];
    const int*   pos   = (const int*)  d_in[3];
    const float* wq    = (const float*)d_in[4];
    const float* kv_b  = (const float*)d_in[5];
    const float* wo    = (const float*)d_in[6];
    const float* cosc  = (const float*)d_in[7];
    const float* sinc  = (const float*)d_in[8];
    float* out = (float*)d_out;

    float *qf, *qcat, *kcat, *S, *olat, *o;
    cudaGetSymbolAddress((void**)&qf,   g_qf);
    cudaGetSymbolAddress((void**)&qcat, g_qcat);
    cudaGetSymbolAddress((void**)&kcat, g_kcat);
    cudaGetSymbolAddress((void**)&S,    g_S);
    cudaGetSymbolAddress((void**)&olat, g_olat);
    cudaGetSymbolAddress((void**)&o,    g_o);

    const float scale = rsqrtf((float)(NOPE + ROPE));

    // 1) qf = q @ wq^T : M=2048 N=3072 K=1536
    gemm_bf16x3<<<dim3(QFW / 128, TT / 128, 1), 256>>>(
        q, wq, qf, QIN,
        QIN, 1, QIN, QFW,
        0, 0, 0, 1.0f, 0);

    // 2) rope + pack
    rope_pack<<<TT, 256>>>(qf, k_c, k_pe, pos, cosc, sinc, qcat, kcat, scale);

    // 3) q_lat per head: M=2048 N=512 K=128, alpha=SCALE -> qcat[:,h,0:512]
    gemm_bf16x3<<<dim3(RANK / 128, TT / 128, H), 256>>>(
        qf, kv_b, qcat, NOPE,
        QFW, RANK, 1, H * DQK,
        (long long)(NOPE + ROPE), (long long)(NOPE + VDIM) * RANK,
        (long long)DQK, scale, 0);

    // 4) S_h = Qcat_h @ Kcat^T : M=2048 N=2048 K=576 (causal tile skip)
    gemm_bf16x3<<<dim3(TT / 128, TT / 128, H), 256>>>(
        qcat, kcat, S, DQK,
        H * DQK, 1, DQK, TT,
        (long long)DQK, 0, (long long)TT * TT, 1.0f, 1);

    // 5) causal softmax in-place (writes exact zeros in masked region)
    softmax_causal<<<dim3(TT, H), 256>>>(S, pos);

    // 6) olat_h = P_h @ k_c : M=2048 N=512 K=2048 (K limited to m0+128)
    gemm_bf16x3<<<dim3(RANK / 128, TT / 128, H), 256>>>(
        S, k_c, olat, TT,
        TT, RANK, 1, H * RANK,
        (long long)TT * TT, 0, (long long)RANK, 1.0f, 2);

    // 7) o[:, h*128:(h+1)*128] = olat_h @ w_uv_h : M=2048 N=128 K=512
    gemm_bf16x3<<<dim3(VDIM / 128, TT / 128, H), 256>>>(
        olat, kv_b + (long long)NOPE * RANK, o, RANK,
        H * RANK, 1, RANK, H * VDIM,
        (long long)RANK, (long long)(NOPE + VDIM) * RANK,
        (long long)VDIM, 1.0f, 0);

    // 8) out = o @ wo^T : M=2048 N=7168 K=2048
    gemm_bf16x3<<<dim3(HID / 128, TT / 128, 1), 256>>>(
        o, wo, out, H * VDIM,
        H * VDIM, 1, H * VDIM, HID,
        0, 0, 0, 1.0f, 0);
}

// round 4
// speedup vs baseline: 2.5589x; 1.1819x over previous
#include <cuda_runtime.h>
#include <cuda_bf16.h>
#include <stdint.h>
#include <math.h>

// ---------------- problem constants ----------------
#define TT    2048
#define H     16
#define NOPE  128
#define ROPE  64
#define VDIM  128
#define RANK  512
#define QIN   1536
#define HID   7168
#define DQK   576
#define QFW   (H * (NOPE + ROPE))   // 3072

static __device__ float g_qf  [(size_t)TT * QFW];
static __device__ float g_qcat[(size_t)TT * H * DQK];
static __device__ float g_kcat[(size_t)TT * DQK];
static __device__ float g_S   [(size_t)H * TT * TT];
static __device__ float g_olat[(size_t)TT * H * RANK];
static __device__ float g_o   [(size_t)TT * H * VDIM];

// ---------------- helpers ----------------
__device__ __forceinline__ uint32_t pack_hi(float a, float b, float& ra, float& rb) {
    __nv_bfloat16 ha = __float2bfloat16(a);
    __nv_bfloat16 hb = __float2bfloat16(b);
    ra = a - __bfloat162float(ha);
    rb = b - __bfloat162float(hb);
    __nv_bfloat162 p; p.x = ha; p.y = hb;
    return *(uint32_t*)&p;
}
__device__ __forceinline__ uint32_t pack_lo(float a, float b) {
    __nv_bfloat162 p;
    p.x = __float2bfloat16(a); p.y = __float2bfloat16(b);
    return *(uint32_t*)&p;
}

#define MMA_BF16(C, A, B0, B1)                                              \
    asm volatile(                                                           \
        "mma.sync.aligned.m16n8k16.row.col.f32.bf16.bf16.f32 "              \
        "{%0,%1,%2,%3},{%4,%5,%6,%7},{%8,%9},{%0,%1,%2,%3};\n"              \
        : "+f"(C[0]), "+f"(C[1]), "+f"(C[2]), "+f"(C[3])                    \
        : "r"(A[0]), "r"(A[1]), "r"(A[2]), "r"(A[3]), "r"(B0), "r"(B1));

#define LDSM_X4(R0, R1, R2, R3, ADDR)                                       \
    asm volatile("ldmatrix.sync.aligned.m8n8.x4.shared.b16 {%0,%1,%2,%3}, [%4];" \
        : "=r"(R0), "=r"(R1), "=r"(R2), "=r"(R3) : "r"(ADDR));

// smem layout (bytes):
//   A: buf0 [hi 8192][lo 8192], buf1 [hi][lo]   -> 0 .. 32767
//   B: same                                      -> 32768 .. 65535
// tile = 128 rows x 32 bf16 (64B/row), XOR swizzle on 16B chunks:
//   byteoff(r, c) = r*64 + ((c ^ ((r>>1)&3)) << 4)
#define SM_TOTAL 65536
#define A_BUF    16384
#define PART_LO  8192
#define B_BASE   32768

// ---------------- compensated-bf16 tensor-core GEMM (ldmatrix + double buffer) ----------------
__global__ __launch_bounds__(256, 1)
void gemm_bf16x3(const float* __restrict__ A, const float* __restrict__ B,
                 float* __restrict__ C, int K,
                 int sa_m, int sb_k, int sb_n, int sc_m,
                 long long aBS, long long bBS, long long cBS,
                 float alpha, int mode)
{
    extern __shared__ char sm[];

    const int m0 = blockIdx.y * 128;
    const int n0 = blockIdx.x * 128;
    if ((mode & 1) && n0 > m0) return;
    int Keff = K;
    if (mode & 2) { int kl = m0 + 128; if (kl < Keff) Keff = kl; }

    A += (long long)blockIdx.z * aBS + (long long)m0 * sa_m;
    B += (long long)blockIdx.z * bBS;
    C += (long long)blockIdx.z * cBS + (long long)m0 * sc_m + n0;

    const int tid  = threadIdx.x;
    const int lane = tid & 31;
    const int wid  = tid >> 5;
    const int warpM = (wid & 3) * 32;
    const int warpN = (wid >> 2) * 64;

    const int srow = tid >> 1;       // 0..127 staging row
    const int sh   = tid & 1;        // k half: 0 -> k0-15, 1 -> k16-31
    const bool bK  = (sb_k == 1);

    float4 pa[4], pb[4];

    float acc[2][8][4];
#pragma unroll
    for (int mi = 0; mi < 2; mi++)
#pragma unroll
        for (int ni = 0; ni < 8; ni++)
#pragma unroll
            for (int j = 0; j < 4; j++) acc[mi][ni][j] = 0.0f;

    // ---- prefetch / staging lambdas ----
    auto loadA = [&](int kt) {
#pragma unroll
        for (int i = 0; i < 4; i++)
            pa[i] = *(const float4*)&A[(long long)srow * sa_m + kt + sh * 16 + i * 4];
    };
    auto loadB = [&](int kt) {
        if (bK) {
#pragma unroll
            for (int i = 0; i < 4; i++)
                pb[i] = *(const float4*)&B[(long long)(n0 + srow) * sb_n + kt + sh * 16 + i * 4];
        } else {
            const int kk = tid >> 5, n4 = tid & 31;
#pragma unroll
            for (int i = 0; i < 4; i++)
                pb[i] = *(const float4*)&B[(long long)(kt + kk + i * 8) * sb_k + n0 + n4 * 4];
        }
    };
    auto storeTileRow = [&](float4* p, int base) {
        uint32_t hi[8], lo[8];
#pragma unroll
        for (int i = 0; i < 4; i++) {
            float rx, ry, rz, rw;
            hi[2*i]   = pack_hi(p[i].x, p[i].y, rx, ry);
            lo[2*i]   = pack_lo(rx, ry);
            hi[2*i+1] = pack_hi(p[i].z, p[i].w, rz, rw);
            lo[2*i+1] = pack_lo(rz, rw);
        }
        const int sw = (srow >> 1) & 3;
        char* p0 = sm + base + srow * 64 + (((sh*2)     ^ sw) << 4);
        char* p1 = sm + base + srow * 64 + (((sh*2 + 1) ^ sw) << 4);
        *(uint4*)p0 = make_uint4(hi[0], hi[1], hi[2], hi[3]);
        *(uint4*)p1 = make_uint4(hi[4], hi[5], hi[6], hi[7]);
        *(uint4*)(p0 + PART_LO) = make_uint4(lo[0], lo[1], lo[2], lo[3]);
        *(uint4*)(p1 + PART_LO) = make_uint4(lo[4], lo[5], lo[6], lo[7]);
    };
    auto storeA = [&](int buf) { storeTileRow(pa, buf * A_BUF); };
    auto storeB = [&](int buf) {
        if (bK) {
            storeTileRow(pb, B_BASE + buf * A_BUF);
        } else {
            const int kk = tid >> 5, n4 = tid & 31;
            const int base = B_BASE + buf * A_BUF;
#pragma unroll
            for (int i = 0; i < 4; i++) {
                int k = kk + i * 8;
                float e[4] = {pb[i].x, pb[i].y, pb[i].z, pb[i].w};
#pragma unroll
                for (int jj = 0; jj < 4; jj++) {
                    int n = n4 * 4 + jj;
                    __nv_bfloat16 hv = __float2bfloat16(e[jj]);
                    __nv_bfloat16 lv = __float2bfloat16(e[jj] - __bfloat162float(hv));
                    int off = n * 64 + ((((k >> 3)) ^ ((n >> 1) & 3)) << 4) + (k & 7) * 2;
                    *(__nv_bfloat16*)(sm + base + off)           = hv;
                    *(__nv_bfloat16*)(sm + base + PART_LO + off) = lv;
                }
            }
        }
    };

    // ---- prologue ----
    loadA(0); loadB(0);
    storeA(0); storeB(0);
    __syncthreads();

    const int nTiles = Keff >> 5;
    for (int t = 0; t < nTiles; t++) {
        const int buf = t & 1;
        const bool more = (t + 1) < nTiles;
        if (more) { loadA((t + 1) << 5); loadB((t + 1) << 5); }

        const int aHi = buf * A_BUF;
        const int bHi = B_BASE + buf * A_BUF;

#pragma unroll
        for (int ks = 0; ks < 2; ks++) {
            // A fragments: 2x (m16 x k16), hi + lo
            uint32_t ah[2][4], al[2][4];
            {
                const int lr = lane & 15;
                const int lc = lane >> 4;
#pragma unroll
                for (int mi = 0; mi < 2; mi++) {
                    int r = warpM + mi * 16 + lr;
                    int ch = 2 * ks + lc;
                    int off = r * 64 + ((ch ^ ((r >> 1) & 3)) << 4);
                    uint32_t ad = (uint32_t)__cvta_generic_to_shared(sm + aHi + off);
                    LDSM_X4(ah[mi][0], ah[mi][1], ah[mi][2], ah[mi][3], ad);
                    LDSM_X4(al[mi][0], al[mi][1], al[mi][2], al[mi][3], ad + PART_LO);
                }
            }
            // B fragments per n16 pair, MMAs interleaved to cap live regs
            const int bn = (lane & 7) + ((lane >> 4) << 3);
            const int bc = 2 * ks + ((lane >> 3) & 1);
#pragma unroll
            for (int p = 0; p < 4; p++) {
                int r = warpN + p * 16 + bn;
                int off = r * 64 + ((bc ^ ((r >> 1) & 3)) << 4);
                uint32_t bd = (uint32_t)__cvta_generic_to_shared(sm + bHi + off);
                uint32_t bh0, bh1, bh2, bh3, bl0, bl1, bl2, bl3;
                LDSM_X4(bh0, bh1, bh2, bh3, bd);
                LDSM_X4(bl0, bl1, bl2, bl3, bd + PART_LO);
#pragma unroll
                for (int mi = 0; mi < 2; mi++) {
                    MMA_BF16(acc[mi][2*p],   ah[mi], bh0, bh1);
                    MMA_BF16(acc[mi][2*p],   ah[mi], bl0, bl1);
                    MMA_BF16(acc[mi][2*p],   al[mi], bh0, bh1);
                    MMA_BF16(acc[mi][2*p+1], ah[mi], bh2, bh3);
                    MMA_BF16(acc[mi][2*p+1], ah[mi], bl2, bl3);
                    MMA_BF16(acc[mi][2*p+1], al[mi], bh2, bh3);
                }
            }
        }

        if (more) { storeA(buf ^ 1); storeB(buf ^ 1); }
        __syncthreads();
    }

    // ---- epilogue ----
    const int g   = lane >> 2;
    const int tig = lane & 3;
#pragma unroll
    for (int mi = 0; mi < 2; mi++)
#pragma unroll
        for (int ni = 0; ni < 8; ni++) {
            int r  = warpM + mi * 16 + g;
            int cc = warpN + ni * 8 + 2 * tig;
            float2 v0 = make_float2(alpha * acc[mi][ni][0], alpha * acc[mi][ni][1]);
            float2 v1 = make_float2(alpha * acc[mi][ni][2], alpha * acc[mi][ni][3]);
            *(float2*)&C[(long long)r * sc_m + cc]       = v0;
            *(float2*)&C[(long long)(r + 8) * sc_m + cc] = v1;
        }
}

// ---------------- RoPE + concat packing ----------------
__global__ void rope_pack(const float* __restrict__ qf, const float* __restrict__ k_c,
                          const float* __restrict__ k_pe, const int* __restrict__ pos,
                          const float* __restrict__ cosc, const float* __restrict__ sinc,
                          float* __restrict__ qcat, float* __restrict__ kcat, float scale)
{
    int t = blockIdx.x;
    int p = pos[t];
    const float* cs = cosc + (long long)p * (ROPE / 2);
    const float* sn = sinc + (long long)p * (ROPE / 2);

    for (int i = threadIdx.x; i < RANK; i += blockDim.x)
        kcat[(long long)t * DQK + i] = k_c[(long long)t * RANK + i];

    for (int j = threadIdx.x; j < ROPE / 2; j += blockDim.x) {
        float x1 = k_pe[(long long)t * ROPE + j];
        float x2 = k_pe[(long long)t * ROPE + j + ROPE / 2];
        float c = cs[j], s = sn[j];
        kcat[(long long)t * DQK + RANK + j]            = x1 * c - x2 * s;
        kcat[(long long)t * DQK + RANK + ROPE / 2 + j] = x2 * c + x1 * s;
    }

    for (int idx = threadIdx.x; idx < H * (ROPE / 2); idx += blockDim.x) {
        int h = idx / (ROPE / 2);
        int j = idx % (ROPE / 2);
        float x1 = qf[(long long)t * QFW + h * (NOPE + ROPE) + NOPE + j];
        float x2 = qf[(long long)t * QFW + h * (NOPE + ROPE) + NOPE + ROPE / 2 + j];
        float c = cs[j], s = sn[j];
        long long base = ((long long)t * H + h) * DQK + RANK;
        qcat[base + j]            = scale * (x1 * c - x2 * s);
        qcat[base + ROPE / 2 + j] = scale * (x2 * c + x1 * s);
    }
}

// ---------------- causal softmax, limited to the causal tile extent ----------------
// GEMM6 reads only columns < ((t>>7)+1)<<7 for row t; beyond that is never touched.
__global__ __launch_bounds__(256)
void softmax_causal(float* __restrict__ S, const int* __restrict__ pos)
{
    const int t = blockIdx.x;
    const int h = blockIdx.y;
    float* row = S + ((long long)h * TT + t) * TT;
    const int pq = pos[t];
    const int limit = ((t >> 7) + 1) << 7;   // multiple of 128, <= TT

    __shared__ float red[256];
    const int tid = threadIdx.x;

    float v[8];
    float m = -1e30f;
#pragma unroll
    for (int i = 0; i < 8; i++) {
        int s = tid + i * 256;
        v[i] = -1e30f;
        if (s < limit && pos[s] <= pq) v[i] = row[s];
        m = fmaxf(m, v[i]);
    }
    red[tid] = m; __syncthreads();
    for (int w = 128; w > 0; w >>= 1) {
        if (tid < w) red[tid] = fmaxf(red[tid], red[tid + w]);
        __syncthreads();
    }
    m = red[0];
    __syncthreads();

    float sum = 0.0f;
#pragma unroll
    for (int i = 0; i < 8; i++) {
        v[i] = __expf(v[i] - m);
        sum += v[i];
    }
    red[tid] = sum; __syncthreads();
    for (int w = 128; w > 0; w >>= 1) {
        if (tid < w) red[tid] += red[tid + w];
        __syncthreads();
    }
    float inv = 1.0f / red[0];

#pragma unroll
    for (int i = 0; i < 8; i++) {
        int s = tid + i * 256;
        if (s < limit) row[s] = v[i] * inv;
    }
}

// ---------------- launch ----------------
extern "C" void kernel_launch(void* const* d_in, const int* in_sizes, int n_in,
                              void* d_out, int out_size)
{
    const float* q     = (const float*)d_in[0];
    const float* k_c   = (const float*)d_in[1];
    const float* k_pe  = (const float*)d_in[2];
    const int*   pos   = (const int*)  d_in[3];
    const float* wq    = (const float*)d_in[4];
    const float* kv_b  = (const float*)d_in[5];
    const float* wo    = (const float*)d_in[6];
    const float* cosc  = (const float*)d_in[7];
    const float* sinc  = (const float*)d_in[8];
    float* out = (float*)d_out;

    float *qf, *qcat, *kcat, *S, *olat, *o;
    cudaGetSymbolAddress((void**)&qf,   g_qf);
    cudaGetSymbolAddress((void**)&qcat, g_qcat);
    cudaGetSymbolAddress((void**)&kcat, g_kcat);
    cudaGetSymbolAddress((void**)&S,    g_S);
    cudaGetSymbolAddress((void**)&olat, g_olat);
    cudaGetSymbolAddress((void**)&o,    g_o);

    cudaFuncSetAttribute(gemm_bf16x3, cudaFuncAttributeMaxDynamicSharedMemorySize, SM_TOTAL);

    const float scale = rsqrtf((float)(NOPE + ROPE));

    // 1) qf = q @ wq^T : M=2048 N=3072 K=1536
    gemm_bf16x3<<<dim3(QFW / 128, TT / 128, 1), 256, SM_TOTAL>>>(
        q, wq, qf, QIN,
        QIN, 1, QIN, QFW,
        0, 0, 0, 1.0f, 0);

    // 2) rope + pack
    rope_pack<<<TT, 256>>>(qf, k_c, k_pe, pos, cosc, sinc, qcat, kcat, scale);

    // 3) q_lat per head: M=2048 N=512 K=128 -> qcat[:,h,0:512], alpha=SCALE
    gemm_bf16x3<<<dim3(RANK / 128, TT / 128, H), 256, SM_TOTAL>>>(
        qf, kv_b, qcat, NOPE,
        QFW, RANK, 1, H * DQK,
        (long long)(NOPE + ROPE), (long long)(NOPE + VDIM) * RANK,
        (long long)DQK, scale, 0);

    // 4) S_h = Qcat_h @ Kcat^T : M=2048 N=2048 K=576 (causal tile skip)
    gemm_bf16x3<<<dim3(TT / 128, TT / 128, H), 256, SM_TOTAL>>>(
        qcat, kcat, S, DQK,
        H * DQK, 1, DQK, TT,
        (long long)DQK, 0, (long long)TT * TT, 1.0f, 1);

    // 5) causal softmax (limited extent)
    softmax_causal<<<dim3(TT, H), 256>>>(S, pos);

    // 6) olat_h = P_h @ k_c : M=2048 N=512 K->m0+128
    gemm_bf16x3<<<dim3(RANK / 128, TT / 128, H), 256, SM_TOTAL>>>(
        S, k_c, olat, TT,
        TT, RANK, 1, H * RANK,
        (long long)TT * TT, 0, (long long)RANK, 1.0f, 2);

    // 7) o[:, h*128:(h+1)*128] = olat_h @ w_uv_h : M=2048 N=128 K=512
    gemm_bf16x3<<<dim3(VDIM / 128, TT / 128, H), 256, SM_TOTAL>>>(
        olat, kv_b + (long long)NOPE * RANK, o, RANK,
        H * RANK, 1, RANK, H * VDIM,
        (long long)RANK, (long long)(NOPE + VDIM) * RANK,
        (long long)VDIM, 1.0f, 0);

    // 8) out = o @ wo^T : M=2048 N=7168 K=2048
    gemm_bf16x3<<<dim3(HID / 128, TT / 128, 1), 256, SM_TOTAL>>>(
        o, wo, out, H * VDIM,
        H * VDIM, 1, H * VDIM, HID,
        0, 0, 0, 1.0f, 0);
}

// round 5
// speedup vs baseline: 3.2858x; 1.2841x over previous
#include <cuda_runtime.h>
#include <cuda_bf16.h>
#include <stdint.h>
#include <math.h>

// ---------------- problem constants ----------------
#define TT    2048
#define H     16
#define NOPE  128
#define ROPE  64
#define VDIM  128
#define RANK  512
#define QIN   1536
#define HID   7168
#define DQK   576
#define QFW   (H * (NOPE + ROPE))   // 3072

typedef __nv_bfloat16 bf16;

// fp32 intermediates
static __device__ float g_qf[(size_t)TT * QFW];
static __device__ float g_S [(size_t)H * TT * TT];

// bf16 hi/lo pairs
static __device__ bf16 g_q_h  [(size_t)TT * QIN],      g_q_l  [(size_t)TT * QIN];
static __device__ bf16 g_wq_h [(size_t)QFW * QIN],     g_wq_l [(size_t)QFW * QIN];
static __device__ bf16 g_qf_h [(size_t)TT * QFW],      g_qf_l [(size_t)TT * QFW];
static __device__ bf16 g_wuk_h[(size_t)H * RANK * NOPE], g_wuk_l[(size_t)H * RANK * NOPE];
static __device__ bf16 g_qc_h [(size_t)TT * H * DQK],  g_qc_l [(size_t)TT * H * DQK];
static __device__ bf16 g_kc_h [(size_t)TT * DQK],      g_kc_l [(size_t)TT * DQK];
static __device__ bf16 g_S_h  [(size_t)H * TT * TT],   g_S_l  [(size_t)H * TT * TT];
static __device__ bf16 g_kT_h [(size_t)RANK * TT],     g_kT_l [(size_t)RANK * TT];
static __device__ bf16 g_ol_h [(size_t)TT * H * RANK], g_ol_l [(size_t)TT * H * RANK];
static __device__ bf16 g_kvb_h[(size_t)H * 256 * RANK], g_kvb_l[(size_t)H * 256 * RANK];
static __device__ bf16 g_o_h  [(size_t)TT * H * VDIM], g_o_l  [(size_t)TT * H * VDIM];
static __device__ bf16 g_wo_h [(size_t)HID * H * VDIM], g_wo_l [(size_t)HID * H * VDIM];

// ---------------- ptx helpers ----------------
#define MMA_BF16(C, A, B0, B1)                                              \
    asm volatile(                                                           \
        "mma.sync.aligned.m16n8k16.row.col.f32.bf16.bf16.f32 "              \
        "{%0,%1,%2,%3},{%4,%5,%6,%7},{%8,%9},{%0,%1,%2,%3};\n"              \
        : "+f"(C[0]), "+f"(C[1]), "+f"(C[2]), "+f"(C[3])                    \
        : "r"(A[0]), "r"(A[1]), "r"(A[2]), "r"(A[3]), "r"(B0), "r"(B1));

#define LDSM_X4(R0, R1, R2, R3, ADDR)                                       \
    asm volatile("ldmatrix.sync.aligned.m8n8.x4.shared.b16 {%0,%1,%2,%3}, [%4];" \
        : "=r"(R0), "=r"(R1), "=r"(R2), "=r"(R3) : "r"(ADDR));

#define CP16(SM, G) asm volatile("cp.async.cg.shared.global [%0], [%1], 16;\n" :: "r"(SM), "l"(G))
#define CP_COMMIT   asm volatile("cp.async.commit_group;\n")
#define CP_WAIT0    asm volatile("cp.async.wait_group 0;\n")
#define CP_WAIT1    asm volatile("cp.async.wait_group 1;\n")

__device__ __forceinline__ void wr_pair(bf16* hi, bf16* lo, long long idx, float v) {
    bf16 h = __float2bfloat16(v);
    hi[idx] = h;
    lo[idx] = __float2bfloat16(v - __bfloat162float(h));
}

// smem: tile = 128 rows x 64 bf16 (128B/row), swizzle: byteoff(r,ch)=r*128+((ch^(r&7))<<4)
#define KT       64
#define PART     16384
#define BUF_SZ   65536          // 4 parts: Ahi Alo Bhi Blo
#define SM_TOTAL 131072

// ---------------- cp.async bf16x3 tensor-core GEMM ----------------
__global__ __launch_bounds__(256, 1)
void gemm_cp(const bf16* __restrict__ Ahi, const bf16* __restrict__ Alo,
             const bf16* __restrict__ Bhi, const bf16* __restrict__ Blo,
             float* __restrict__ Cfp, bf16* __restrict__ Chi, bf16* __restrict__ Clo,
             int K, int sa, int sb, int sc,
             long long aBS, long long bBS, long long cBS,
             float alpha, int mode)
{
    extern __shared__ char sm[];

    const int m0 = blockIdx.y * 128;
    const int n0 = blockIdx.x * 128;
    if ((mode & 1) && n0 > m0) return;
    int Keff = K;
    if (mode & 2) { int kl = m0 + 128; if (kl < Keff) Keff = kl; }

    Ahi += (long long)blockIdx.z * aBS + (long long)m0 * sa;
    Alo += (long long)blockIdx.z * aBS + (long long)m0 * sa;
    Bhi += (long long)blockIdx.z * bBS + (long long)n0 * sb;
    Blo += (long long)blockIdx.z * bBS + (long long)n0 * sb;
    const long long cOff = (long long)blockIdx.z * cBS + (long long)m0 * sc + n0;

    const int tid  = threadIdx.x;
    const int lane = tid & 31;
    const int wid  = tid >> 5;
    const int warpM = (wid & 3) * 32;
    const int warpN = (wid >> 2) * 64;
    const int srow  = tid >> 1;
    const int shalf = (tid & 1) * 4;

    const uint32_t smBase = (uint32_t)__cvta_generic_to_shared(sm);

    float acc[2][8][4];
#pragma unroll
    for (int mi = 0; mi < 2; mi++)
#pragma unroll
        for (int ni = 0; ni < 8; ni++)
#pragma unroll
            for (int j = 0; j < 4; j++) acc[mi][ni][j] = 0.0f;

    auto issueTile = [&](int t) {
        const int kt = t * KT;
        const uint32_t sb0 = smBase + (t & 1) * BUF_SZ;
        const bf16* srcs[4] = {
            Ahi + (long long)srow * sa + kt,
            Alo + (long long)srow * sa + kt,
            Bhi + (long long)srow * sb + kt,
            Blo + (long long)srow * sb + kt };
#pragma unroll
        for (int p = 0; p < 4; p++) {
            const uint32_t pb = sb0 + p * PART + srow * 128;
            const bf16* g = srcs[p] + shalf * 8;
#pragma unroll
            for (int i = 0; i < 4; i++) {
                int ch = shalf + i;
                CP16(pb + ((ch ^ (srow & 7)) << 4), g + i * 8);
            }
        }
    };

    issueTile(0); CP_COMMIT;

    const int nT = Keff / KT;
    for (int t = 0; t < nT; t++) {
        if (t + 1 < nT) { issueTile(t + 1); CP_COMMIT; CP_WAIT1; }
        else            { CP_WAIT0; }
        __syncthreads();

        const uint32_t aHi = smBase + (t & 1) * BUF_SZ;
        const uint32_t aLo = aHi + PART;
        const uint32_t bHi = aLo + PART;
        const uint32_t bLo = bHi + PART;

#pragma unroll
        for (int ks = 0; ks < 4; ks++) {
            uint32_t ah[2][4], al[2][4];
            {
                const int lr = lane & 15;
                const int lc = lane >> 4;
#pragma unroll
                for (int mi = 0; mi < 2; mi++) {
                    int r  = warpM + mi * 16 + lr;
                    int ch = 2 * ks + lc;
                    uint32_t off = r * 128 + ((ch ^ (r & 7)) << 4);
                    LDSM_X4(ah[mi][0], ah[mi][1], ah[mi][2], ah[mi][3], aHi + off);
                    LDSM_X4(al[mi][0], al[mi][1], al[mi][2], al[mi][3], aLo + off);
                }
            }
            const int bn = (lane & 7) + ((lane >> 4) << 3);
            const int bc = 2 * ks + ((lane >> 3) & 1);
#pragma unroll
            for (int p = 0; p < 4; p++) {
                int r = warpN + p * 16 + bn;
                uint32_t off = r * 128 + ((bc ^ (r & 7)) << 4);
                uint32_t bh0, bh1, bh2, bh3, bl0, bl1, bl2, bl3;
                LDSM_X4(bh0, bh1, bh2, bh3, bHi + off);
                LDSM_X4(bl0, bl1, bl2, bl3, bLo + off);
#pragma unroll
                for (int mi = 0; mi < 2; mi++) {
                    MMA_BF16(acc[mi][2*p],   ah[mi], bh0, bh1);
                    MMA_BF16(acc[mi][2*p],   ah[mi], bl0, bl1);
                    MMA_BF16(acc[mi][2*p],   al[mi], bh0, bh1);
                    MMA_BF16(acc[mi][2*p+1], ah[mi], bh2, bh3);
                    MMA_BF16(acc[mi][2*p+1], ah[mi], bl2, bl3);
                    MMA_BF16(acc[mi][2*p+1], al[mi], bh2, bh3);
                }
            }
        }
        __syncthreads();
    }

    // ---- epilogue ----
    const int g   = lane >> 2;
    const int tig = lane & 3;
#pragma unroll
    for (int mi = 0; mi < 2; mi++)
#pragma unroll
        for (int ni = 0; ni < 8; ni++) {
            int r  = warpM + mi * 16 + g;
            int cc = warpN + ni * 8 + 2 * tig;
            float v0 = alpha * acc[mi][ni][0], v1 = alpha * acc[mi][ni][1];
            float v2 = alpha * acc[mi][ni][2], v3 = alpha * acc[mi][ni][3];
            long long i0 = cOff + (long long)r * sc + cc;
            long long i1 = cOff + (long long)(r + 8) * sc + cc;
            if (Cfp) {
                *(float2*)&Cfp[i0] = make_float2(v0, v1);
                *(float2*)&Cfp[i1] = make_float2(v2, v3);
            }
            if (Chi) {
                wr_pair(Chi, Clo, i0,     v0);
                wr_pair(Chi, Clo, i0 + 1, v1);
                wr_pair(Chi, Clo, i1,     v2);
                wr_pair(Chi, Clo, i1 + 1, v3);
            }
        }
}

// ---------------- conversion kernels ----------------
__global__ void cvt_pair(const float4* __restrict__ src,
                         __nv_bfloat162* __restrict__ hi, __nv_bfloat162* __restrict__ lo,
                         int n4)
{
    int i = blockIdx.x * 256 + threadIdx.x;
    if (i >= n4) return;
    float4 v = src[i];
    bf16 hx = __float2bfloat16(v.x), hy = __float2bfloat16(v.y);
    bf16 hz = __float2bfloat16(v.z), hw = __float2bfloat16(v.w);
    __nv_bfloat162 h0; h0.x = hx; h0.y = hy;
    __nv_bfloat162 h1; h1.x = hz; h1.y = hw;
    hi[2*i] = h0; hi[2*i+1] = h1;
    __nv_bfloat162 l0, l1;
    l0.x = __float2bfloat16(v.x - __bfloat162float(hx));
    l0.y = __float2bfloat16(v.y - __bfloat162float(hy));
    l1.x = __float2bfloat16(v.z - __bfloat162float(hz));
    l1.y = __float2bfloat16(v.w - __bfloat162float(hw));
    lo[2*i] = l0; lo[2*i+1] = l1;
}

// dst[q][p] = src[p][q], with batch strides
__global__ void tr_cvt(const float* __restrict__ src, bf16* __restrict__ hi, bf16* __restrict__ lo,
                       int P, int Q, long long srcBS, long long dstBS)
{
    __shared__ float t[32][33];
    const int p0 = blockIdx.y * 32, q0 = blockIdx.x * 32;
    const float* s = src + (long long)blockIdx.z * srcBS;
    t[threadIdx.y][threadIdx.x] = s[(long long)(p0 + threadIdx.y) * Q + q0 + threadIdx.x];
    __syncthreads();
    long long o = (long long)blockIdx.z * dstBS + (long long)(q0 + threadIdx.y) * P + p0 + threadIdx.x;
    wr_pair(hi, lo, o, t[threadIdx.x][threadIdx.y]);
}

// ---------------- RoPE + pack (writes bf16 pairs) ----------------
__global__ void rope_pack(const float* __restrict__ qf, const float* __restrict__ k_c,
                          const float* __restrict__ k_pe, const int* __restrict__ pos,
                          const float* __restrict__ cosc, const float* __restrict__ sinc,
                          float scale)
{
    int t = blockIdx.x;
    int p = pos[t];
    const float* cs = cosc + (long long)p * (ROPE / 2);
    const float* sn = sinc + (long long)p * (ROPE / 2);

    for (int i = threadIdx.x; i < RANK; i += blockDim.x)
        wr_pair(g_kc_h, g_kc_l, (long long)t * DQK + i, k_c[(long long)t * RANK + i]);

    for (int j = threadIdx.x; j < ROPE / 2; j += blockDim.x) {
        float x1 = k_pe[(long long)t * ROPE + j];
        float x2 = k_pe[(long long)t * ROPE + j + ROPE / 2];
        float c = cs[j], s = sn[j];
        wr_pair(g_kc_h, g_kc_l, (long long)t * DQK + RANK + j,            x1 * c - x2 * s);
        wr_pair(g_kc_h, g_kc_l, (long long)t * DQK + RANK + ROPE / 2 + j, x2 * c + x1 * s);
    }

    for (int idx = threadIdx.x; idx < H * (ROPE / 2); idx += blockDim.x) {
        int h = idx / (ROPE / 2);
        int j = idx % (ROPE / 2);
        float x1 = qf[(long long)t * QFW + h * (NOPE + ROPE) + NOPE + j];
        float x2 = qf[(long long)t * QFW + h * (NOPE + ROPE) + NOPE + ROPE / 2 + j];
        float c = cs[j], s = sn[j];
        long long base = ((long long)t * H + h) * DQK + RANK;
        wr_pair(g_qc_h, g_qc_l, base + j,            scale * (x1 * c - x2 * s));
        wr_pair(g_qc_h, g_qc_l, base + ROPE / 2 + j, scale * (x2 * c + x1 * s));
    }
}

// ---------------- causal softmax: fp32 in, bf16 pair out ----------------
__global__ __launch_bounds__(256)
void softmax_causal(const float* __restrict__ S, bf16* __restrict__ Ph, bf16* __restrict__ Pl,
                    const int* __restrict__ pos)
{
    const int t = blockIdx.x;
    const int h = blockIdx.y;
    const long long rb = ((long long)h * TT + t) * TT;
    const int pq = pos[t];
    const int limit = ((t >> 7) + 1) << 7;

    __shared__ float red[256];
    const int tid = threadIdx.x;

    float v[8];
    float m = -1e30f;
#pragma unroll
    for (int i = 0; i < 8; i++) {
        int s = tid + i * 256;
        v[i] = -1e30f;
        if (s < limit && pos[s] <= pq) v[i] = S[rb + s];
        m = fmaxf(m, v[i]);
    }
    red[tid] = m; __syncthreads();
    for (int w = 128; w > 0; w >>= 1) {
        if (tid < w) red[tid] = fmaxf(red[tid], red[tid + w]);
        __syncthreads();
    }
    m = red[0];
    __syncthreads();

    float sum = 0.0f;
#pragma unroll
    for (int i = 0; i < 8; i++) {
        v[i] = __expf(v[i] - m);
        sum += v[i];
    }
    red[tid] = sum; __syncthreads();
    for (int w = 128; w > 0; w >>= 1) {
        if (tid < w) red[tid] += red[tid + w];
        __syncthreads();
    }
    float inv = 1.0f / red[0];

#pragma unroll
    for (int i = 0; i < 8; i++) {
        int s = tid + i * 256;
        if (s < limit) wr_pair(Ph, Pl, rb + s, v[i] * inv);
    }
}

// ---------------- launch ----------------
extern "C" void kernel_launch(void* const* d_in, const int* in_sizes, int n_in,
                              void* d_out, int out_size)
{
    const float* q     = (const float*)d_in[0];
    const float* k_c   = (const float*)d_in[1];
    const float* k_pe  = (const float*)d_in[2];
    const int*   pos   = (const int*)  d_in[3];
    const float* wq    = (const float*)d_in[4];
    const float* kv_b  = (const float*)d_in[5];
    const float* wo    = (const float*)d_in[6];
    const float* cosc  = (const float*)d_in[7];
    const float* sinc  = (const float*)d_in[8];
    float* out = (float*)d_out;

    float *qf, *S;
    cudaGetSymbolAddress((void**)&qf, g_qf);
    cudaGetSymbolAddress((void**)&S,  g_S);
    bf16 *q_h,*q_l,*wq_h,*wq_l,*qf_h,*qf_l,*wuk_h,*wuk_l,*qc_h,*qc_l,*kc_h,*kc_l;
    bf16 *S_h,*S_l,*kT_h,*kT_l,*ol_h,*ol_l,*kvb_h,*kvb_l,*o_h,*o_l,*wo_h,*wo_l;
    cudaGetSymbolAddress((void**)&q_h,  g_q_h);  cudaGetSymbolAddress((void**)&q_l,  g_q_l);
    cudaGetSymbolAddress((void**)&wq_h, g_wq_h); cudaGetSymbolAddress((void**)&wq_l, g_wq_l);
    cudaGetSymbolAddress((void**)&qf_h, g_qf_h); cudaGetSymbolAddress((void**)&qf_l, g_qf_l);
    cudaGetSymbolAddress((void**)&wuk_h,g_wuk_h);cudaGetSymbolAddress((void**)&wuk_l,g_wuk_l);
    cudaGetSymbolAddress((void**)&qc_h, g_qc_h); cudaGetSymbolAddress((void**)&qc_l, g_qc_l);
    cudaGetSymbolAddress((void**)&kc_h, g_kc_h); cudaGetSymbolAddress((void**)&kc_l, g_kc_l);
    cudaGetSymbolAddress((void**)&S_h,  g_S_h);  cudaGetSymbolAddress((void**)&S_l,  g_S_l);
    cudaGetSymbolAddress((void**)&kT_h, g_kT_h); cudaGetSymbolAddress((void**)&kT_l, g_kT_l);
    cudaGetSymbolAddress((void**)&ol_h, g_ol_h); cudaGetSymbolAddress((void**)&ol_l, g_ol_l);
    cudaGetSymbolAddress((void**)&kvb_h,g_kvb_h);cudaGetSymbolAddress((void**)&kvb_l,g_kvb_l);
    cudaGetSymbolAddress((void**)&o_h,  g_o_h);  cudaGetSymbolAddress((void**)&o_l,  g_o_l);
    cudaGetSymbolAddress((void**)&wo_h, g_wo_h); cudaGetSymbolAddress((void**)&wo_l, g_wo_l);

    cudaFuncSetAttribute(gemm_cp, cudaFuncAttributeMaxDynamicSharedMemorySize, SM_TOTAL);

    const float scale = rsqrtf((float)(NOPE + ROPE));

    // ---- operand preconversion ----
    {
        int n4;
        n4 = TT * QIN / 4;
        cvt_pair<<<(n4 + 255) / 256, 256>>>((const float4*)q,  (__nv_bfloat162*)q_h,  (__nv_bfloat162*)q_l,  n4);
        n4 = QFW * QIN / 4;
        cvt_pair<<<(n4 + 255) / 256, 256>>>((const float4*)wq, (__nv_bfloat162*)wq_h, (__nv_bfloat162*)wq_l, n4);
        n4 = H * 256 * RANK / 4;
        cvt_pair<<<(n4 + 255) / 256, 256>>>((const float4*)kv_b, (__nv_bfloat162*)kvb_h, (__nv_bfloat162*)kvb_l, n4);
        n4 = HID * H * VDIM / 4;
        cvt_pair<<<(n4 + 255) / 256, 256>>>((const float4*)wo, (__nv_bfloat162*)wo_h, (__nv_bfloat162*)wo_l, n4);
        // wukT[h][r][c] = kv_b[h*256+c][r]
        tr_cvt<<<dim3(RANK / 32, NOPE / 32, H), dim3(32, 32)>>>(
            kv_b, wuk_h, wuk_l, NOPE, RANK, (long long)256 * RANK, (long long)RANK * NOPE);
        // kcT[r][s] = k_c[s][r]
        tr_cvt<<<dim3(RANK / 32, TT / 32, 1), dim3(32, 32)>>>(
            k_c, kT_h, kT_l, TT, RANK, 0, 0);
    }

    // 1) qf = q @ wq^T : M=2048 N=3072 K=1536  (fp32 + bf16 pair out)
    gemm_cp<<<dim3(QFW / 128, TT / 128, 1), 256, SM_TOTAL>>>(
        q_h, q_l, wq_h, wq_l, qf, qf_h, qf_l,
        QIN, QIN, QIN, QFW, 0, 0, 0, 1.0f, 0);

    // 2) rope + pack (kcat pair, qcat pe cols pair)
    rope_pack<<<TT, 256>>>(qf, k_c, k_pe, pos, cosc, sinc, scale);

    // 3) q_lat per head: M=2048 N=512 K=128 -> qcat pair cols 0..511, alpha=SCALE
    gemm_cp<<<dim3(RANK / 128, TT / 128, H), 256, SM_TOTAL>>>(
        qf_h, qf_l, wuk_h, wuk_l, nullptr, qc_h, qc_l,
        NOPE, QFW, NOPE, H * DQK,
        (long long)(NOPE + ROPE), (long long)RANK * NOPE, (long long)DQK, scale, 0);

    // 4) S_h = Qcat_h @ Kcat^T : M=2048 N=2048 K=576 (causal tile skip, fp32 out)
    gemm_cp<<<dim3(TT / 128, TT / 128, H), 256, SM_TOTAL>>>(
        qc_h, qc_l, kc_h, kc_l, S, nullptr, nullptr,
        DQK, H * DQK, DQK, TT,
        (long long)DQK, 0, (long long)TT * TT, 1.0f, 1);

    // 5) softmax -> bf16 pair probs
    softmax_causal<<<dim3(TT, H), 256>>>(S, S_h, S_l, pos);

    // 6) olat_h = P_h @ k_c : M=2048 N=512, K limited to m0+128
    gemm_cp<<<dim3(RANK / 128, TT / 128, H), 256, SM_TOTAL>>>(
        S_h, S_l, kT_h, kT_l, nullptr, ol_h, ol_l,
        TT, TT, TT, H * RANK,
        (long long)TT * TT, 0, (long long)RANK, 1.0f, 2);

    // 7) o_h = olat_h @ w_uv_h : M=2048 N=128 K=512
    gemm_cp<<<dim3(VDIM / 128, TT / 128, H), 256, SM_TOTAL>>>(
        ol_h, ol_l, kvb_h + (long long)NOPE * RANK, kvb_l + (long long)NOPE * RANK,
        nullptr, o_h, o_l,
        RANK, H * RANK, RANK, H * VDIM,
        (long long)RANK, (long long)256 * RANK, (long long)VDIM, 1.0f, 0);

    // 8) out = o @ wo^T : M=2048 N=7168 K=2048 (fp32 out)
    gemm_cp<<<dim3(HID / 128, TT / 128, 1), 256, SM_TOTAL>>>(
        o_h, o_l, wo_h, wo_l, out, nullptr, nullptr,
        H * VDIM, H * VDIM, H * VDIM, HID, 0, 0, 0, 1.0f, 0);
}

// round 7
// speedup vs baseline: 3.3101x; 1.0074x over previous
#include <cuda_runtime.h>
#include <cuda_bf16.h>
#include <stdint.h>
#include <math.h>

// ---------------- problem constants ----------------
#define TT    2048
#define H     16
#define NOPE  128
#define ROPE  64
#define VDIM  128
#define RANK  512
#define QIN   1536
#define HID   7168
#define DQK   576
#define QFW   (H * (NOPE + ROPE))   // 3072

typedef __nv_bfloat16 bf16;

// fp32 intermediates
static __device__ float g_qf[(size_t)TT * QFW];
static __device__ float g_S [(size_t)H * TT * TT];

// bf16 hi/lo pairs
static __device__ bf16 g_q_h  [(size_t)TT * QIN],      g_q_l  [(size_t)TT * QIN];
static __device__ bf16 g_wq_h [(size_t)QFW * QIN],     g_wq_l [(size_t)QFW * QIN];
static __device__ bf16 g_qf_h [(size_t)TT * QFW],      g_qf_l [(size_t)TT * QFW];
static __device__ bf16 g_wuk_h[(size_t)H * RANK * NOPE], g_wuk_l[(size_t)H * RANK * NOPE];
static __device__ bf16 g_qc_h [(size_t)TT * H * DQK],  g_qc_l [(size_t)TT * H * DQK];
static __device__ bf16 g_kc_h [(size_t)TT * DQK],      g_kc_l [(size_t)TT * DQK];
static __device__ bf16 g_S_h  [(size_t)H * TT * TT],   g_S_l  [(size_t)H * TT * TT];
static __device__ bf16 g_kT_h [(size_t)RANK * TT],     g_kT_l [(size_t)RANK * TT];
static __device__ bf16 g_ol_h [(size_t)TT * H * RANK], g_ol_l [(size_t)TT * H * RANK];
static __device__ bf16 g_kvb_h[(size_t)H * 256 * RANK], g_kvb_l[(size_t)H * 256 * RANK];
static __device__ bf16 g_o_h  [(size_t)TT * H * VDIM], g_o_l  [(size_t)TT * H * VDIM];
static __device__ bf16 g_wo_h [(size_t)HID * H * VDIM], g_wo_l [(size_t)HID * H * VDIM];

// ---------------- ptx helpers ----------------
#define MMA_BF16(C, A, B0, B1)                                              \
    asm volatile(                                                           \
        "mma.sync.aligned.m16n8k16.row.col.f32.bf16.bf16.f32 "              \
        "{%0,%1,%2,%3},{%4,%5,%6,%7},{%8,%9},{%0,%1,%2,%3};\n"              \
        : "+f"(C[0]), "+f"(C[1]), "+f"(C[2]), "+f"(C[3])                    \
        : "r"(A[0]), "r"(A[1]), "r"(A[2]), "r"(A[3]), "r"(B0), "r"(B1));

#define LDSM_X4(R0, R1, R2, R3, ADDR)                                       \
    asm volatile("ldmatrix.sync.aligned.m8n8.x4.shared.b16 {%0,%1,%2,%3}, [%4];" \
        : "=r"(R0), "=r"(R1), "=r"(R2), "=r"(R3) : "r"(ADDR));

#define CP16(SM, G) asm volatile("cp.async.cg.shared.global [%0], [%1], 16;\n" :: "r"(SM), "l"(G))
#define CP_COMMIT   asm volatile("cp.async.commit_group;\n")
#define CP_WAIT0    asm volatile("cp.async.wait_group 0;\n")
#define CP_WAIT1    asm volatile("cp.async.wait_group 1;\n")

__device__ __forceinline__ void wr_pair(bf16* hi, bf16* lo, long long idx, float v) {
    bf16 h = __float2bfloat16(v);
    hi[idx] = h;
    lo[idx] = __float2bfloat16(v - __bfloat162float(h));
}

// smem: tile = 128 rows x 64 bf16 (128B/row), swizzle: byteoff(r,ch)=r*128+((ch^(r&7))<<4)
#define KT       64
#define PART     16384
#define BUF_SZ   65536          // 4 parts: Ahi Alo Bhi Blo
#define SM_TOTAL 131072

// ---------------- cp.async bf16x3 tensor-core GEMM ----------------
__global__ __launch_bounds__(256, 1)
void gemm_cp(const bf16* __restrict__ Ahi, const bf16* __restrict__ Alo,
             const bf16* __restrict__ Bhi, const bf16* __restrict__ Blo,
             float* __restrict__ Cfp, bf16* __restrict__ Chi, bf16* __restrict__ Clo,
             int K, int sa, int sb, int sc,
             long long aBS, long long bBS, long long cBS,
             float alpha, int mode)
{
    extern __shared__ char sm[];

    const int m0 = blockIdx.y * 128;
    const int n0 = blockIdx.x * 128;
    if ((mode & 1) && n0 > m0) return;
    int Keff = K;
    if (mode & 2) { int kl = m0 + 128; if (kl < Keff) Keff = kl; }

    Ahi += (long long)blockIdx.z * aBS + (long long)m0 * sa;
    Alo += (long long)blockIdx.z * aBS + (long long)m0 * sa;
    Bhi += (long long)blockIdx.z * bBS + (long long)n0 * sb;
    Blo += (long long)blockIdx.z * bBS + (long long)n0 * sb;
    const long long cOff = (long long)blockIdx.z * cBS + (long long)m0 * sc + n0;

    const int tid  = threadIdx.x;
    const int lane = tid & 31;
    const int wid  = tid >> 5;
    const int warpM = (wid & 3) * 32;
    const int warpN = (wid >> 2) * 64;
    const int srow  = tid >> 1;
    const int shalf = (tid & 1) * 4;

    const uint32_t smBase = (uint32_t)__cvta_generic_to_shared(sm);

    float acc[2][8][4];
#pragma unroll
    for (int mi = 0; mi < 2; mi++)
#pragma unroll
        for (int ni = 0; ni < 8; ni++)
#pragma unroll
            for (int j = 0; j < 4; j++) acc[mi][ni][j] = 0.0f;

    auto issueTile = [&](int t) {
        const int kt = t * KT;
        const uint32_t sb0 = smBase + (t & 1) * BUF_SZ;
        const bf16* srcs[4] = {
            Ahi + (long long)srow * sa + kt,
            Alo + (long long)srow * sa + kt,
            Bhi + (long long)srow * sb + kt,
            Blo + (long long)srow * sb + kt };
#pragma unroll
        for (int p = 0; p < 4; p++) {
            const uint32_t pb = sb0 + p * PART + srow * 128;
            const bf16* g = srcs[p] + shalf * 8;
#pragma unroll
            for (int i = 0; i < 4; i++) {
                int ch = shalf + i;
                CP16(pb + ((ch ^ (srow & 7)) << 4), g + i * 8);
            }
        }
    };

    issueTile(0); CP_COMMIT;

    const int nT = Keff / KT;
    for (int t = 0; t < nT; t++) {
        if (t + 1 < nT) { issueTile(t + 1); CP_COMMIT; CP_WAIT1; }
        else            { CP_WAIT0; }
        __syncthreads();

        const uint32_t aHi = smBase + (t & 1) * BUF_SZ;
        const uint32_t aLo = aHi + PART;
        const uint32_t bHi = aLo + PART;
        const uint32_t bLo = bHi + PART;

#pragma unroll
        for (int ks = 0; ks < 4; ks++) {
            // ---- load all fragments for this k16 slice ----
            uint32_t ah[2][4], al[2][4];
            {
                const int lr = lane & 15;
                const int lc = lane >> 4;
#pragma unroll
                for (int mi = 0; mi < 2; mi++) {
                    int r  = warpM + mi * 16 + lr;
                    int ch = 2 * ks + lc;
                    uint32_t off = r * 128 + ((ch ^ (r & 7)) << 4);
                    LDSM_X4(ah[mi][0], ah[mi][1], ah[mi][2], ah[mi][3], aHi + off);
                    LDSM_X4(al[mi][0], al[mi][1], al[mi][2], al[mi][3], aLo + off);
                }
            }
            uint32_t bh[4][4], bl[4][4];
            {
                const int bn = (lane & 7) + ((lane >> 4) << 3);
                const int bc = 2 * ks + ((lane >> 3) & 1);
#pragma unroll
                for (int p = 0; p < 4; p++) {
                    int r = warpN + p * 16 + bn;
                    uint32_t off = r * 128 + ((bc ^ (r & 7)) << 4);
                    LDSM_X4(bh[p][0], bh[p][1], bh[p][2], bh[p][3], bHi + off);
                    LDSM_X4(bl[p][0], bl[p][1], bl[p][2], bl[p][3], bLo + off);
                }
            }
            // ---- MMAs term-major: same-acc reuse distance = 16 issues ----
#pragma unroll
            for (int p = 0; p < 4; p++)
#pragma unroll
                for (int mi = 0; mi < 2; mi++) {
                    MMA_BF16(acc[mi][2*p],   ah[mi], bh[p][0], bh[p][1]);
                    MMA_BF16(acc[mi][2*p+1], ah[mi], bh[p][2], bh[p][3]);
                }
#pragma unroll
            for (int p = 0; p < 4; p++)
#pragma unroll
                for (int mi = 0; mi < 2; mi++) {
                    MMA_BF16(acc[mi][2*p],   ah[mi], bl[p][0], bl[p][1]);
                    MMA_BF16(acc[mi][2*p+1], ah[mi], bl[p][2], bl[p][3]);
                }
#pragma unroll
            for (int p = 0; p < 4; p++)
#pragma unroll
                for (int mi = 0; mi < 2; mi++) {
                    MMA_BF16(acc[mi][2*p],   al[mi], bh[p][0], bh[p][1]);
                    MMA_BF16(acc[mi][2*p+1], al[mi], bh[p][2], bh[p][3]);
                }
        }
        __syncthreads();
    }

    // ---- epilogue ----
    const int g   = lane >> 2;
    const int tig = lane & 3;
#pragma unroll
    for (int mi = 0; mi < 2; mi++)
#pragma unroll
        for (int ni = 0; ni < 8; ni++) {
            int r  = warpM + mi * 16 + g;
            int cc = warpN + ni * 8 + 2 * tig;
            float v0 = alpha * acc[mi][ni][0], v1 = alpha * acc[mi][ni][1];
            float v2 = alpha * acc[mi][ni][2], v3 = alpha * acc[mi][ni][3];
            long long i0 = cOff + (long long)r * sc + cc;
            long long i1 = cOff + (long long)(r + 8) * sc + cc;
            if (Cfp) {
                *(float2*)&Cfp[i0] = make_float2(v0, v1);
                *(float2*)&Cfp[i1] = make_float2(v2, v3);
            }
            if (Chi) {
                wr_pair(Chi, Clo, i0,     v0);
                wr_pair(Chi, Clo, i0 + 1, v1);
                wr_pair(Chi, Clo, i1,     v2);
                wr_pair(Chi, Clo, i1 + 1, v3);
            }
        }
}

// ---------------- conversion kernels ----------------
__global__ void cvt_pair(const float4* __restrict__ src,
                         __nv_bfloat162* __restrict__ hi, __nv_bfloat162* __restrict__ lo,
                         int n4)
{
    int i = blockIdx.x * 256 + threadIdx.x;
    if (i >= n4) return;
    float4 v = src[i];
    bf16 hx = __float2bfloat16(v.x), hy = __float2bfloat16(v.y);
    bf16 hz = __float2bfloat16(v.z), hw = __float2bfloat16(v.w);
    __nv_bfloat162 h0; h0.x = hx; h0.y = hy;
    __nv_bfloat162 h1; h1.x = hz; h1.y = hw;
    hi[2*i] = h0; hi[2*i+1] = h1;
    __nv_bfloat162 l0, l1;
    l0.x = __float2bfloat16(v.x - __bfloat162float(hx));
    l0.y = __float2bfloat16(v.y - __bfloat162float(hy));
    l1.x = __float2bfloat16(v.z - __bfloat162float(hz));
    l1.y = __float2bfloat16(v.w - __bfloat162float(hw));
    lo[2*i] = l0; lo[2*i+1] = l1;
}

// dst[q][p] = src[p][q], with batch strides
__global__ void tr_cvt(const float* __restrict__ src, bf16* __restrict__ hi, bf16* __restrict__ lo,
                       int P, int Q, long long srcBS, long long dstBS)
{
    __shared__ float t[32][33];
    const int p0 = blockIdx.y * 32, q0 = blockIdx.x * 32;
    const float* s = src + (long long)blockIdx.z * srcBS;
    t[threadIdx.y][threadIdx.x] = s[(long long)(p0 + threadIdx.y) * Q + q0 + threadIdx.x];
    __syncthreads();
    long long o = (long long)blockIdx.z * dstBS + (long long)(q0 + threadIdx.y) * P + p0 + threadIdx.x;
    wr_pair(hi, lo, o, t[threadIdx.x][threadIdx.y]);
}

// ---------------- RoPE + pack (writes bf16 pairs) ----------------
__global__ void rope_pack(const float* __restrict__ qf, const float* __restrict__ k_c,
                          const float* __restrict__ k_pe, const int* __restrict__ pos,
                          const float* __restrict__ cosc, const float* __restrict__ sinc,
                          float scale)
{
    int t = blockIdx.x;
    int p = pos[t];
    const float* cs = cosc + (long long)p * (ROPE / 2);
    const float* sn = sinc + (long long)p * (ROPE / 2);

    for (int i = threadIdx.x; i < RANK; i += blockDim.x)
        wr_pair(g_kc_h, g_kc_l, (long long)t * DQK + i, k_c[(long long)t * RANK + i]);

    for (int j = threadIdx.x; j < ROPE / 2; j += blockDim.x) {
        float x1 = k_pe[(long long)t * ROPE + j];
        float x2 = k_pe[(long long)t * ROPE + j + ROPE / 2];
        float c = cs[j], s = sn[j];
        wr_pair(g_kc_h, g_kc_l, (long long)t * DQK + RANK + j,            x1 * c - x2 * s);
        wr_pair(g_kc_h, g_kc_l, (long long)t * DQK + RANK + ROPE / 2 + j, x2 * c + x1 * s);
    }

    for (int idx = threadIdx.x; idx < H * (ROPE / 2); idx += blockDim.x) {
        int h = idx / (ROPE / 2);
        int j = idx % (ROPE / 2);
        float x1 = qf[(long long)t * QFW + h * (NOPE + ROPE) + NOPE + j];
        float x2 = qf[(long long)t * QFW + h * (NOPE + ROPE) + NOPE + ROPE / 2 + j];
        float c = cs[j], s = sn[j];
        long long base = ((long long)t * H + h) * DQK + RANK;
        wr_pair(g_qc_h, g_qc_l, base + j,            scale * (x1 * c - x2 * s));
        wr_pair(g_qc_h, g_qc_l, base + ROPE / 2 + j, scale * (x2 * c + x1 * s));
    }
}

// ---------------- causal softmax: fp32 in, bf16 pair out ----------------
__global__ __launch_bounds__(256)
void softmax_causal(const float* __restrict__ S, bf16* __restrict__ Ph, bf16* __restrict__ Pl,
                    const int* __restrict__ pos)
{
    const int t = blockIdx.x;
    const int h = blockIdx.y;
    const long long rb = ((long long)h * TT + t) * TT;
    const int pq = pos[t];
    const int limit = ((t >> 7) + 1) << 7;

    __shared__ float red[256];
    const int tid = threadIdx.x;

    float v[8];
    float m = -1e30f;
#pragma unroll
    for (int i = 0; i < 8; i++) {
        int s = tid + i * 256;
        v[i] = -1e30f;
        if (s < limit && pos[s] <= pq) v[i] = S[rb + s];
        m = fmaxf(m, v[i]);
    }
    red[tid] = m; __syncthreads();
    for (int w = 128; w > 0; w >>= 1) {
        if (tid < w) red[tid] = fmaxf(red[tid], red[tid + w]);
        __syncthreads();
    }
    m = red[0];
    __syncthreads();

    float sum = 0.0f;
#pragma unroll
    for (int i = 0; i < 8; i++) {
        v[i] = __expf(v[i] - m);
        sum += v[i];
    }
    red[tid] = sum; __syncthreads();
    for (int w = 128; w > 0; w >>= 1) {
        if (tid < w) red[tid] += red[tid + w];
        __syncthreads();
    }
    float inv = 1.0f / red[0];

#pragma unroll
    for (int i = 0; i < 8; i++) {
        int s = tid + i * 256;
        if (s < limit) wr_pair(Ph, Pl, rb + s, v[i] * inv);
    }
}

// ---------------- launch ----------------
extern "C" void kernel_launch(void* const* d_in, const int* in_sizes, int n_in,
                              void* d_out, int out_size)
{
    const float* q     = (const float*)d_in[0];
    const float* k_c   = (const float*)d_in[1];
    const float* k_pe  = (const float*)d_in[2];
    const int*   pos   = (const int*)  d_in[3];
    const float* wq    = (const float*)d_in[4];
    const float* kv_b  = (const float*)d_in[5];
    const float* wo    = (const float*)d_in[6];
    const float* cosc  = (const float*)d_in[7];
    const float* sinc  = (const float*)d_in[8];
    float* out = (float*)d_out;

    float *qf, *S;
    cudaGetSymbolAddress((void**)&qf, g_qf);
    cudaGetSymbolAddress((void**)&S,  g_S);
    bf16 *q_h,*q_l,*wq_h,*wq_l,*qf_h,*qf_l,*wuk_h,*wuk_l,*qc_h,*qc_l,*kc_h,*kc_l;
    bf16 *S_h,*S_l,*kT_h,*kT_l,*ol_h,*ol_l,*kvb_h,*kvb_l,*o_h,*o_l,*wo_h,*wo_l;
    cudaGetSymbolAddress((void**)&q_h,  g_q_h);  cudaGetSymbolAddress((void**)&q_l,  g_q_l);
    cudaGetSymbolAddress((void**)&wq_h, g_wq_h); cudaGetSymbolAddress((void**)&wq_l, g_wq_l);
    cudaGetSymbolAddress((void**)&qf_h, g_qf_h); cudaGetSymbolAddress((void**)&qf_l, g_qf_l);
    cudaGetSymbolAddress((void**)&wuk_h,g_wuk_h);cudaGetSymbolAddress((void**)&wuk_l,g_wuk_l);
    cudaGetSymbolAddress((void**)&qc_h, g_qc_h); cudaGetSymbolAddress((void**)&qc_l, g_qc_l);
    cudaGetSymbolAddress((void**)&kc_h, g_kc_h); cudaGetSymbolAddress((void**)&kc_l, g_kc_l);
    cudaGetSymbolAddress((void**)&S_h,  g_S_h);  cudaGetSymbolAddress((void**)&S_l,  g_S_l);
    cudaGetSymbolAddress((void**)&kT_h, g_kT_h); cudaGetSymbolAddress((void**)&kT_l, g_kT_l);
    cudaGetSymbolAddress((void**)&ol_h, g_ol_h); cudaGetSymbolAddress((void**)&ol_l, g_ol_l);
    cudaGetSymbolAddress((void**)&kvb_h,g_kvb_h);cudaGetSymbolAddress((void**)&kvb_l,g_kvb_l);
    cudaGetSymbolAddress((void**)&o_h,  g_o_h);  cudaGetSymbolAddress((void**)&o_l,  g_o_l);
    cudaGetSymbolAddress((void**)&wo_h, g_wo_h); cudaGetSymbolAddress((void**)&wo_l, g_wo_l);

    cudaFuncSetAttribute(gemm_cp, cudaFuncAttributeMaxDynamicSharedMemorySize, SM_TOTAL);

    const float scale = rsqrtf((float)(NOPE + ROPE));

    // ---- operand preconversion ----
    {
        int n4;
        n4 = TT * QIN / 4;
        cvt_pair<<<(n4 + 255) / 256, 256>>>((const float4*)q,  (__nv_bfloat162*)q_h,  (__nv_bfloat162*)q_l,  n4);
        n4 = QFW * QIN / 4;
        cvt_pair<<<(n4 + 255) / 256, 256>>>((const float4*)wq, (__nv_bfloat162*)wq_h, (__nv_bfloat162*)wq_l, n4);
        n4 = H * 256 * RANK / 4;
        cvt_pair<<<(n4 + 255) / 256, 256>>>((const float4*)kv_b, (__nv_bfloat162*)kvb_h, (__nv_bfloat162*)kvb_l, n4);
        n4 = HID * H * VDIM / 4;
        cvt_pair<<<(n4 + 255) / 256, 256>>>((const float4*)wo, (__nv_bfloat162*)wo_h, (__nv_bfloat162*)wo_l, n4);
        tr_cvt<<<dim3(RANK / 32, NOPE / 32, H), dim3(32, 32)>>>(
            kv_b, wuk_h, wuk_l, NOPE, RANK, (long long)256 * RANK, (long long)RANK * NOPE);
        tr_cvt<<<dim3(RANK / 32, TT / 32, 1), dim3(32, 32)>>>(
            k_c, kT_h, kT_l, TT, RANK, 0, 0);
    }

    // 1) qf = q @ wq^T : M=2048 N=3072 K=1536  (fp32 + bf16 pair out)
    gemm_cp<<<dim3(QFW / 128, TT / 128, 1), 256, SM_TOTAL>>>(
        q_h, q_l, wq_h, wq_l, qf, qf_h, qf_l,
        QIN, QIN, QIN, QFW, 0, 0, 0, 1.0f, 0);

    // 2) rope + pack
    rope_pack<<<TT, 256>>>(qf, k_c, k_pe, pos, cosc, sinc, scale);

    // 3) q_lat per head: M=2048 N=512 K=128 -> qcat pair cols 0..511, alpha=SCALE
    gemm_cp<<<dim3(RANK / 128, TT / 128, H), 256, SM_TOTAL>>>(
        qf_h, qf_l, wuk_h, wuk_l, nullptr, qc_h, qc_l,
        NOPE, QFW, NOPE, H * DQK,
        (long long)(NOPE + ROPE), (long long)RANK * NOPE, (long long)DQK, scale, 0);

    // 4) S_h = Qcat_h @ Kcat^T : M=2048 N=2048 K=576 (causal tile skip, fp32 out)
    gemm_cp<<<dim3(TT / 128, TT / 128, H), 256, SM_TOTAL>>>(
        qc_h, qc_l, kc_h, kc_l, S, nullptr, nullptr,
        DQK, H * DQK, DQK, TT,
        (long long)DQK, 0, (long long)TT * TT, 1.0f, 1);

    // 5) softmax -> bf16 pair probs
    softmax_causal<<<dim3(TT, H), 256>>>(S, S_h, S_l, pos);

    // 6) olat_h = P_h @ k_c : M=2048 N=512, K limited to m0+128
    gemm_cp<<<dim3(RANK / 128, TT / 128, H), 256, SM_TOTAL>>>(
        S_h, S_l, kT_h, kT_l, nullptr, ol_h, ol_l,
        TT, TT, TT, H * RANK,
        (long long)TT * TT, 0, (long long)RANK, 1.0f, 2);

    // 7) o_h = olat_h @ w_uv_h : M=2048 N=128 K=512
    gemm_cp<<<dim3(VDIM / 128, TT / 128, H), 256, SM_TOTAL>>>(
        ol_h, ol_l, kvb_h + (long long)NOPE * RANK, kvb_l + (long long)NOPE * RANK,
        nullptr, o_h, o_l,
        RANK, H * RANK, RANK, H * VDIM,
        (long long)RANK, (long long)256 * RANK, (long long)VDIM, 1.0f, 0);

    // 8) out = o @ wo^T : M=2048 N=7168 K=2048 (fp32 out)
    gemm_cp<<<dim3(HID / 128, TT / 128, 1), 256, SM_TOTAL>>>(
        o_h, o_l, wo_h, wo_l, out, nullptr, nullptr,
        H * VDIM, H * VDIM, H * VDIM, HID, 0, 0, 0, 1.0f, 0);
}

// round 8
// speedup vs baseline: 3.8747x; 1.1706x over previous
#include <cuda_runtime.h>
#include <cuda_bf16.h>
#include <stdint.h>
#include <math.h>

// ---------------- problem constants ----------------
#define TT    2048
#define H     16
#define NOPE  128
#define ROPE  64
#define VDIM  128
#define RANK  512
#define QIN   1536
#define HID   7168
#define DQK   576
#define QFW   (H * (NOPE + ROPE))   // 3072

typedef __nv_bfloat16 bf16;

// fp32 intermediates
static __device__ float g_qf[(size_t)TT * QFW];
static __device__ float g_S [(size_t)H * TT * TT];

// bf16 hi/lo pairs
static __device__ bf16 g_q_h  [(size_t)TT * QIN],      g_q_l  [(size_t)TT * QIN];
static __device__ bf16 g_wq_h [(size_t)QFW * QIN],     g_wq_l [(size_t)QFW * QIN];
static __device__ bf16 g_qf_h [(size_t)TT * QFW],      g_qf_l [(size_t)TT * QFW];
static __device__ bf16 g_wuk_h[(size_t)H * RANK * NOPE], g_wuk_l[(size_t)H * RANK * NOPE];
static __device__ bf16 g_qc_h [(size_t)TT * H * DQK],  g_qc_l [(size_t)TT * H * DQK];
static __device__ bf16 g_kc_h [(size_t)TT * DQK],      g_kc_l [(size_t)TT * DQK];
static __device__ bf16 g_S_h  [(size_t)H * TT * TT],   g_S_l  [(size_t)H * TT * TT];
static __device__ bf16 g_kT_h [(size_t)RANK * TT],     g_kT_l [(size_t)RANK * TT];
static __device__ bf16 g_ol_h [(size_t)TT * H * RANK], g_ol_l [(size_t)TT * H * RANK];
static __device__ bf16 g_kvb_h[(size_t)H * 256 * RANK], g_kvb_l[(size_t)H * 256 * RANK];
static __device__ bf16 g_o_h  [(size_t)TT * H * VDIM], g_o_l  [(size_t)TT * H * VDIM];
static __device__ bf16 g_wo_h [(size_t)HID * H * VDIM], g_wo_l [(size_t)HID * H * VDIM];

// ---------------- ptx helpers ----------------
#define MMA_BF16(C, A, B0, B1)                                              \
    asm volatile(                                                           \
        "mma.sync.aligned.m16n8k16.row.col.f32.bf16.bf16.f32 "              \
        "{%0,%1,%2,%3},{%4,%5,%6,%7},{%8,%9},{%0,%1,%2,%3};\n"              \
        : "+f"(C[0]), "+f"(C[1]), "+f"(C[2]), "+f"(C[3])                    \
        : "r"(A[0]), "r"(A[1]), "r"(A[2]), "r"(A[3]), "r"(B0), "r"(B1));

#define LDSM_X4(R0, R1, R2, R3, ADDR)                                       \
    asm volatile("ldmatrix.sync.aligned.m8n8.x4.shared.b16 {%0,%1,%2,%3}, [%4];" \
        : "=r"(R0), "=r"(R1), "=r"(R2), "=r"(R3) : "r"(ADDR));

#define CP16(SM, G) asm volatile("cp.async.cg.shared.global [%0], [%1], 16;\n" :: "r"(SM), "l"(G))
#define CP_COMMIT   asm volatile("cp.async.commit_group;\n")
#define CP_WAIT0    asm volatile("cp.async.wait_group 0;\n")
#define CP_WAIT1    asm volatile("cp.async.wait_group 1;\n")

__device__ __forceinline__ void wr_pair(bf16* hi, bf16* lo, long long idx, float v) {
    bf16 h = __float2bfloat16(v);
    hi[idx] = h;
    lo[idx] = __float2bfloat16(v - __bfloat162float(h));
}

// smem: tile = 128 rows x 32 bf16 (64B/row), swizzle: byteoff(r,ch)=r*64+((ch^((r>>1)&3))<<4)
// 4 parts per stage (Ahi Alo Bhi Blo), 2 stages -> 64KB/CTA -> 2 CTAs/SM
#define KT       32
#define PART     8192
#define BUF_SZ   32768
#define SM_TOTAL 65536

// ---------------- cp.async bf16x3 tensor-core GEMM (2 CTAs/SM) ----------------
__global__ __launch_bounds__(256, 2)
void gemm_cp(const bf16* __restrict__ Ahi, const bf16* __restrict__ Alo,
             const bf16* __restrict__ Bhi, const bf16* __restrict__ Blo,
             float* __restrict__ Cfp, bf16* __restrict__ Chi, bf16* __restrict__ Clo,
             int K, int sa, int sb, int sc,
             long long aBS, long long bBS, long long cBS,
             float alpha, int mode)
{
    extern __shared__ char sm[];

    const int m0 = blockIdx.y * 128;
    const int n0 = blockIdx.x * 128;
    if ((mode & 1) && n0 > m0) return;
    int Keff = K;
    if (mode & 2) { int kl = m0 + 128; if (kl < Keff) Keff = kl; }

    Ahi += (long long)blockIdx.z * aBS + (long long)m0 * sa;
    Alo += (long long)blockIdx.z * aBS + (long long)m0 * sa;
    Bhi += (long long)blockIdx.z * bBS + (long long)n0 * sb;
    Blo += (long long)blockIdx.z * bBS + (long long)n0 * sb;
    const long long cOff = (long long)blockIdx.z * cBS + (long long)m0 * sc + n0;

    const int tid  = threadIdx.x;
    const int lane = tid & 31;
    const int wid  = tid >> 5;
    const int warpM = (wid & 3) * 32;
    const int warpN = (wid >> 2) * 64;
    const int srow  = tid >> 1;          // staging row 0..127
    const int sch0  = (tid & 1) * 2;     // first of two 16B chunks (0..3)

    const uint32_t smBase = (uint32_t)__cvta_generic_to_shared(sm);

    float acc[2][8][4];
#pragma unroll
    for (int mi = 0; mi < 2; mi++)
#pragma unroll
        for (int ni = 0; ni < 8; ni++)
#pragma unroll
            for (int j = 0; j < 4; j++) acc[mi][ni][j] = 0.0f;

    auto issueTile = [&](int t) {
        const int kt = t * KT;
        const uint32_t sb0 = smBase + (t & 1) * BUF_SZ;
        const bf16* srcs[4] = {
            Ahi + (long long)srow * sa + kt,
            Alo + (long long)srow * sa + kt,
            Bhi + (long long)srow * sb + kt,
            Blo + (long long)srow * sb + kt };
        const int sw = (srow >> 1) & 3;
#pragma unroll
        for (int p = 0; p < 4; p++) {
            const uint32_t pb = sb0 + p * PART + srow * 64;
#pragma unroll
            for (int i = 0; i < 2; i++) {
                int ch = sch0 + i;
                CP16(pb + ((ch ^ sw) << 4), srcs[p] + ch * 8);
            }
        }
    };

    issueTile(0); CP_COMMIT;

    const int nT = Keff / KT;
    for (int t = 0; t < nT; t++) {
        if (t + 1 < nT) { issueTile(t + 1); CP_COMMIT; CP_WAIT1; }
        else            { CP_WAIT0; }
        __syncthreads();

        const uint32_t aHi = smBase + (t & 1) * BUF_SZ;
        const uint32_t aLo = aHi + PART;
        const uint32_t bHi = aLo + PART;
        const uint32_t bLo = bHi + PART;

#pragma unroll
        for (int ks = 0; ks < 2; ks++) {
            uint32_t ah[2][4], al[2][4];
            {
                const int lr = lane & 15;
                const int lc = lane >> 4;
#pragma unroll
                for (int mi = 0; mi < 2; mi++) {
                    int r  = warpM + mi * 16 + lr;
                    int ch = 2 * ks + lc;
                    uint32_t off = r * 64 + ((ch ^ ((r >> 1) & 3)) << 4);
                    LDSM_X4(ah[mi][0], ah[mi][1], ah[mi][2], ah[mi][3], aHi + off);
                    LDSM_X4(al[mi][0], al[mi][1], al[mi][2], al[mi][3], aLo + off);
                }
            }
            const int bn = (lane & 7) + ((lane >> 4) << 3);
            const int bc = 2 * ks + ((lane >> 3) & 1);
#pragma unroll
            for (int p = 0; p < 4; p++) {
                int r = warpN + p * 16 + bn;
                uint32_t off = r * 64 + ((bc ^ ((r >> 1) & 3)) << 4);
                uint32_t bh0, bh1, bh2, bh3, bl0, bl1, bl2, bl3;
                LDSM_X4(bh0, bh1, bh2, bh3, bHi + off);
                LDSM_X4(bl0, bl1, bl2, bl3, bLo + off);
#pragma unroll
                for (int mi = 0; mi < 2; mi++) {
                    MMA_BF16(acc[mi][2*p],   ah[mi], bh0, bh1);
                    MMA_BF16(acc[mi][2*p],   ah[mi], bl0, bl1);
                    MMA_BF16(acc[mi][2*p],   al[mi], bh0, bh1);
                    MMA_BF16(acc[mi][2*p+1], ah[mi], bh2, bh3);
                    MMA_BF16(acc[mi][2*p+1], ah[mi], bl2, bl3);
                    MMA_BF16(acc[mi][2*p+1], al[mi], bh2, bh3);
                }
            }
        }
        __syncthreads();
    }

    // ---- epilogue ----
    const int g   = lane >> 2;
    const int tig = lane & 3;
#pragma unroll
    for (int mi = 0; mi < 2; mi++)
#pragma unroll
        for (int ni = 0; ni < 8; ni++) {
            int r  = warpM + mi * 16 + g;
            int cc = warpN + ni * 8 + 2 * tig;
            float v0 = alpha * acc[mi][ni][0], v1 = alpha * acc[mi][ni][1];
            float v2 = alpha * acc[mi][ni][2], v3 = alpha * acc[mi][ni][3];
            long long i0 = cOff + (long long)r * sc + cc;
            long long i1 = cOff + (long long)(r + 8) * sc + cc;
            if (Cfp) {
                *(float2*)&Cfp[i0] = make_float2(v0, v1);
                *(float2*)&Cfp[i1] = make_float2(v2, v3);
            }
            if (Chi) {
                __nv_bfloat162 h2, l2;
                h2.x = __float2bfloat16(v0); h2.y = __float2bfloat16(v1);
                l2.x = __float2bfloat16(v0 - __bfloat162float(h2.x));
                l2.y = __float2bfloat16(v1 - __bfloat162float(h2.y));
                *(__nv_bfloat162*)&Chi[i0] = h2;
                *(__nv_bfloat162*)&Clo[i0] = l2;
                h2.x = __float2bfloat16(v2); h2.y = __float2bfloat16(v3);
                l2.x = __float2bfloat16(v2 - __bfloat162float(h2.x));
                l2.y = __float2bfloat16(v3 - __bfloat162float(h2.y));
                *(__nv_bfloat162*)&Chi[i1] = h2;
                *(__nv_bfloat162*)&Clo[i1] = l2;
            }
        }
}

// ---------------- conversion kernels ----------------
__global__ void cvt_pair(const float4* __restrict__ src,
                         __nv_bfloat162* __restrict__ hi, __nv_bfloat162* __restrict__ lo,
                         int n4)
{
    int i = blockIdx.x * 256 + threadIdx.x;
    if (i >= n4) return;
    float4 v = src[i];
    bf16 hx = __float2bfloat16(v.x), hy = __float2bfloat16(v.y);
    bf16 hz = __float2bfloat16(v.z), hw = __float2bfloat16(v.w);
    __nv_bfloat162 h0; h0.x = hx; h0.y = hy;
    __nv_bfloat162 h1; h1.x = hz; h1.y = hw;
    hi[2*i] = h0; hi[2*i+1] = h1;
    __nv_bfloat162 l0, l1;
    l0.x = __float2bfloat16(v.x - __bfloat162float(hx));
    l0.y = __float2bfloat16(v.y - __bfloat162float(hy));
    l1.x = __float2bfloat16(v.z - __bfloat162float(hz));
    l1.y = __float2bfloat16(v.w - __bfloat162float(hw));
    lo[2*i] = l0; lo[2*i+1] = l1;
}

// dst[q][p] = src[p][q], with batch strides
__global__ void tr_cvt(const float* __restrict__ src, bf16* __restrict__ hi, bf16* __restrict__ lo,
                       int P, int Q, long long srcBS, long long dstBS)
{
    __shared__ float t[32][33];
    const int p0 = blockIdx.y * 32, q0 = blockIdx.x * 32;
    const float* s = src + (long long)blockIdx.z * srcBS;
    t[threadIdx.y][threadIdx.x] = s[(long long)(p0 + threadIdx.y) * Q + q0 + threadIdx.x];
    __syncthreads();
    long long o = (long long)blockIdx.z * dstBS + (long long)(q0 + threadIdx.y) * P + p0 + threadIdx.x;
    wr_pair(hi, lo, o, t[threadIdx.x][threadIdx.y]);
}

// ---------------- RoPE + pack (writes bf16 pairs) ----------------
__global__ void rope_pack(const float* __restrict__ qf, const float* __restrict__ k_c,
                          const float* __restrict__ k_pe, const int* __restrict__ pos,
                          const float* __restrict__ cosc, const float* __restrict__ sinc,
                          float scale)
{
    int t = blockIdx.x;
    int p = pos[t];
    const float* cs = cosc + (long long)p * (ROPE / 2);
    const float* sn = sinc + (long long)p * (ROPE / 2);

    for (int i = threadIdx.x; i < RANK; i += blockDim.x)
        wr_pair(g_kc_h, g_kc_l, (long long)t * DQK + i, k_c[(long long)t * RANK + i]);

    for (int j = threadIdx.x; j < ROPE / 2; j += blockDim.x) {
        float x1 = k_pe[(long long)t * ROPE + j];
        float x2 = k_pe[(long long)t * ROPE + j + ROPE / 2];
        float c = cs[j], s = sn[j];
        wr_pair(g_kc_h, g_kc_l, (long long)t * DQK + RANK + j,            x1 * c - x2 * s);
        wr_pair(g_kc_h, g_kc_l, (long long)t * DQK + RANK + ROPE / 2 + j, x2 * c + x1 * s);
    }

    for (int idx = threadIdx.x; idx < H * (ROPE / 2); idx += blockDim.x) {
        int h = idx / (ROPE / 2);
        int j = idx % (ROPE / 2);
        float x1 = qf[(long long)t * QFW + h * (NOPE + ROPE) + NOPE + j];
        float x2 = qf[(long long)t * QFW + h * (NOPE + ROPE) + NOPE + ROPE / 2 + j];
        float c = cs[j], s = sn[j];
        long long base = ((long long)t * H + h) * DQK + RANK;
        wr_pair(g_qc_h, g_qc_l, base + j,            scale * (x1 * c - x2 * s));
        wr_pair(g_qc_h, g_qc_l, base + ROPE / 2 + j, scale * (x2 * c + x1 * s));
    }
}

// ---------------- causal softmax: fp32 in, bf16 pair out ----------------
__global__ __launch_bounds__(256)
void softmax_causal(const float* __restrict__ S, bf16* __restrict__ Ph, bf16* __restrict__ Pl,
                    const int* __restrict__ pos)
{
    const int t = blockIdx.x;
    const int h = blockIdx.y;
    const long long rb = ((long long)h * TT + t) * TT;
    const int pq = pos[t];
    const int limit = ((t >> 7) + 1) << 7;

    __shared__ float red[256];
    const int tid = threadIdx.x;

    float v[8];
    float m = -1e30f;
#pragma unroll
    for (int i = 0; i < 8; i++) {
        int s = tid + i * 256;
        v[i] = -1e30f;
        if (s < limit && pos[s] <= pq) v[i] = S[rb + s];
        m = fmaxf(m, v[i]);
    }
    red[tid] = m; __syncthreads();
    for (int w = 128; w > 0; w >>= 1) {
        if (tid < w) red[tid] = fmaxf(red[tid], red[tid + w]);
        __syncthreads();
    }
    m = red[0];
    __syncthreads();

    float sum = 0.0f;
#pragma unroll
    for (int i = 0; i < 8; i++) {
        v[i] = __expf(v[i] - m);
        sum += v[i];
    }
    red[tid] = sum; __syncthreads();
    for (int w = 128; w > 0; w >>= 1) {
        if (tid < w) red[tid] += red[tid + w];
        __syncthreads();
    }
    float inv = 1.0f / red[0];

#pragma unroll
    for (int i = 0; i < 8; i++) {
        int s = tid + i * 256;
        if (s < limit) wr_pair(Ph, Pl, rb + s, v[i] * inv);
    }
}

// ---------------- launch ----------------
extern "C" void kernel_launch(void* const* d_in, const int* in_sizes, int n_in,
                              void* d_out, int out_size)
{
    const float* q     = (const float*)d_in[0];
    const float* k_c   = (const float*)d_in[1];
    const float* k_pe  = (const float*)d_in[2];
    const int*   pos   = (const int*)  d_in[3];
    const float* wq    = (const float*)d_in[4];
    const float* kv_b  = (const float*)d_in[5];
    const float* wo    = (const float*)d_in[6];
    const float* cosc  = (const float*)d_in[7];
    const float* sinc  = (const float*)d_in[8];
    float* out = (float*)d_out;

    float *qf, *S;
    cudaGetSymbolAddress((void**)&qf, g_qf);
    cudaGetSymbolAddress((void**)&S,  g_S);
    bf16 *q_h,*q_l,*wq_h,*wq_l,*qf_h,*qf_l,*wuk_h,*wuk_l,*qc_h,*qc_l,*kc_h,*kc_l;
    bf16 *S_h,*S_l,*kT_h,*kT_l,*ol_h,*ol_l,*kvb_h,*kvb_l,*o_h,*o_l,*wo_h,*wo_l;
    cudaGetSymbolAddress((void**)&q_h,  g_q_h);  cudaGetSymbolAddress((void**)&q_l,  g_q_l);
    cudaGetSymbolAddress((void**)&wq_h, g_wq_h); cudaGetSymbolAddress((void**)&wq_l, g_wq_l);
    cudaGetSymbolAddress((void**)&qf_h, g_qf_h); cudaGetSymbolAddress((void**)&qf_l, g_qf_l);
    cudaGetSymbolAddress((void**)&wuk_h,g_wuk_h);cudaGetSymbolAddress((void**)&wuk_l,g_wuk_l);
    cudaGetSymbolAddress((void**)&qc_h, g_qc_h); cudaGetSymbolAddress((void**)&qc_l, g_qc_l);
    cudaGetSymbolAddress((void**)&kc_h, g_kc_h); cudaGetSymbolAddress((void**)&kc_l, g_kc_l);
    cudaGetSymbolAddress((void**)&S_h,  g_S_h);  cudaGetSymbolAddress((void**)&S_l,  g_S_l);
    cudaGetSymbolAddress((void**)&kT_h, g_kT_h); cudaGetSymbolAddress((void**)&kT_l, g_kT_l);
    cudaGetSymbolAddress((void**)&ol_h, g_ol_h); cudaGetSymbolAddress((void**)&ol_l, g_ol_l);
    cudaGetSymbolAddress((void**)&kvb_h,g_kvb_h);cudaGetSymbolAddress((void**)&kvb_l,g_kvb_l);
    cudaGetSymbolAddress((void**)&o_h,  g_o_h);  cudaGetSymbolAddress((void**)&o_l,  g_o_l);
    cudaGetSymbolAddress((void**)&wo_h, g_wo_h); cudaGetSymbolAddress((void**)&wo_l, g_wo_l);

    cudaFuncSetAttribute(gemm_cp, cudaFuncAttributeMaxDynamicSharedMemorySize, SM_TOTAL);

    const float scale = rsqrtf((float)(NOPE + ROPE));

    // ---- operand preconversion ----
    {
        int n4;
        n4 = TT * QIN / 4;
        cvt_pair<<<(n4 + 255) / 256, 256>>>((const float4*)q,  (__nv_bfloat162*)q_h,  (__nv_bfloat162*)q_l,  n4);
        n4 = QFW * QIN / 4;
        cvt_pair<<<(n4 + 255) / 256, 256>>>((const float4*)wq, (__nv_bfloat162*)wq_h, (__nv_bfloat162*)wq_l, n4);
        n4 = H * 256 * RANK / 4;
        cvt_pair<<<(n4 + 255) / 256, 256>>>((const float4*)kv_b, (__nv_bfloat162*)kvb_h, (__nv_bfloat162*)kvb_l, n4);
        n4 = HID * H * VDIM / 4;
        cvt_pair<<<(n4 + 255) / 256, 256>>>((const float4*)wo, (__nv_bfloat162*)wo_h, (__nv_bfloat162*)wo_l, n4);
        tr_cvt<<<dim3(RANK / 32, NOPE / 32, H), dim3(32, 32)>>>(
            kv_b, wuk_h, wuk_l, NOPE, RANK, (long long)256 * RANK, (long long)RANK * NOPE);
        tr_cvt<<<dim3(RANK / 32, TT / 32, 1), dim3(32, 32)>>>(
            k_c, kT_h, kT_l, TT, RANK, 0, 0);
    }

    // 1) qf = q @ wq^T : M=2048 N=3072 K=1536  (fp32 + bf16 pair out)
    gemm_cp<<<dim3(QFW / 128, TT / 128, 1), 256, SM_TOTAL>>>(
        q_h, q_l, wq_h, wq_l, qf, qf_h, qf_l,
        QIN, QIN, QIN, QFW, 0, 0, 0, 1.0f, 0);

    // 2) rope + pack
    rope_pack<<<TT, 256>>>(qf, k_c, k_pe, pos, cosc, sinc, scale);

    // 3) q_lat per head: M=2048 N=512 K=128 -> qcat pair cols 0..511, alpha=SCALE
    gemm_cp<<<dim3(RANK / 128, TT / 128, H), 256, SM_TOTAL>>>(
        qf_h, qf_l, wuk_h, wuk_l, nullptr, qc_h, qc_l,
        NOPE, QFW, NOPE, H * DQK,
        (long long)(NOPE + ROPE), (long long)RANK * NOPE, (long long)DQK, scale, 0);

    // 4) S_h = Qcat_h @ Kcat^T : M=2048 N=2048 K=576 (causal tile skip, fp32 out)
    gemm_cp<<<dim3(TT / 128, TT / 128, H), 256, SM_TOTAL>>>(
        qc_h, qc_l, kc_h, kc_l, S, nullptr, nullptr,
        DQK, H * DQK, DQK, TT,
        (long long)DQK, 0, (long long)TT * TT, 1.0f, 1);

    // 5) softmax -> bf16 pair probs
    softmax_causal<<<dim3(TT, H), 256>>>(S, S_h, S_l, pos);

    // 6) olat_h = P_h @ k_c : M=2048 N=512, K limited to m0+128
    gemm_cp<<<dim3(RANK / 128, TT / 128, H), 256, SM_TOTAL>>>(
        S_h, S_l, kT_h, kT_l, nullptr, ol_h, ol_l,
        TT, TT, TT, H * RANK,
        (long long)TT * TT, 0, (long long)RANK, 1.0f, 2);

    // 7) o_h = olat_h @ w_uv_h : M=2048 N=128 K=512
    gemm_cp<<<dim3(VDIM / 128, TT / 128, H), 256, SM_TOTAL>>>(
        ol_h, ol_l, kvb_h + (long long)NOPE * RANK, kvb_l + (long long)NOPE * RANK,
        nullptr, o_h, o_l,
        RANK, H * RANK, RANK, H * VDIM,
        (long long)RANK, (long long)256 * RANK, (long long)VDIM, 1.0f, 0);

    // 8) out = o @ wo^T : M=2048 N=7168 K=2048 (fp32 out)
    gemm_cp<<<dim3(HID / 128, TT / 128, 1), 256, SM_TOTAL>>>(
        o_h, o_l, wo_h, wo_l, out, nullptr, nullptr,
        H * VDIM, H * VDIM, H * VDIM, HID, 0, 0, 0, 1.0f, 0);
}